// round 13
// baseline (speedup 1.0000x reference)
#include <cuda_runtime.h>
#include <cuda_bf16.h>
#include <cstdint>
#include <cstddef>

// Problem constants: B=2, S=2048, D=1024, H=16, HD=64
constexpr int Bc  = 2;
constexpr int Sc  = 2048;
constexpr int Dc  = 1024;
constexpr int Hc  = 16;
constexpr int HDc = 64;
constexpr int Mc  = Bc * Sc;   // 4096

// ---------------------------------------------------------------------------
// Static device scratch (all bf16 hi/lo pairs)
// ---------------------------------------------------------------------------
__device__ __nv_bfloat16 g_xh[(size_t)Mc * Dc];   // activations hi (reused for attn-out)
__device__ __nv_bfloat16 g_xl[(size_t)Mc * Dc];   // activations lo

__device__ __nv_bfloat16 g_wqh[(size_t)Dc * Dc];
__device__ __nv_bfloat16 g_wql[(size_t)Dc * Dc];
__device__ __nv_bfloat16 g_wkh[(size_t)Dc * Dc];
__device__ __nv_bfloat16 g_wkl[(size_t)Dc * Dc];
__device__ __nv_bfloat16 g_wvh[(size_t)Dc * Dc];
__device__ __nv_bfloat16 g_wvl[(size_t)Dc * Dc];
__device__ __nv_bfloat16 g_woh[(size_t)Dc * Dc];
__device__ __nv_bfloat16 g_wol[(size_t)Dc * Dc];

__device__ __nv_bfloat16 g_qh[(size_t)Bc * Hc * Sc * HDc];
__device__ __nv_bfloat16 g_ql[(size_t)Bc * Hc * Sc * HDc];
__device__ __nv_bfloat16 g_kh[(size_t)Bc * Hc * Sc * HDc];
__device__ __nv_bfloat16 g_kl[(size_t)Bc * Hc * Sc * HDc];
__device__ __nv_bfloat16 g_vh[(size_t)Bc * Hc * Sc * HDc];
__device__ __nv_bfloat16 g_vl[(size_t)Bc * Hc * Sc * HDc];

// ---------------------------------------------------------------------------
// PTX helpers (baseline ISA only — compute_103 safe)
// ---------------------------------------------------------------------------
__device__ __forceinline__ uint32_t smem_to_u32(const void* p) {
    uint32_t a;
    asm("{ .reg .u64 t; cvta.to.shared.u64 t, %1; cvt.u32.u64 %0, t; }"
        : "=r"(a) : "l"(p));
    return a;
}
__device__ __forceinline__ void cp_async16(uint32_t dst, const void* src) {
    asm volatile("cp.async.cg.shared.global [%0], [%1], 16;"
                 :: "r"(dst), "l"(src) : "memory");
}
__device__ __forceinline__ void cp_commit() {
    asm volatile("cp.async.commit_group;" ::: "memory");
}
__device__ __forceinline__ void cp_wait0() {
    asm volatile("cp.async.wait_group 0;" ::: "memory");
}
__device__ __forceinline__ void cp_wait1() {
    asm volatile("cp.async.wait_group 1;" ::: "memory");
}
__device__ __forceinline__ void ldsm_x4(uint32_t (&r)[4], uint32_t addr) {
    asm volatile("ldmatrix.sync.aligned.m8n8.x4.shared.b16 {%0,%1,%2,%3}, [%4];"
                 : "=r"(r[0]), "=r"(r[1]), "=r"(r[2]), "=r"(r[3]) : "r"(addr));
}
__device__ __forceinline__ void ldsm_x4_trans(uint32_t (&r)[4], uint32_t addr) {
    asm volatile("ldmatrix.sync.aligned.m8n8.x4.trans.shared.b16 {%0,%1,%2,%3}, [%4];"
                 : "=r"(r[0]), "=r"(r[1]), "=r"(r[2]), "=r"(r[3]) : "r"(addr));
}
__device__ __forceinline__ void mma_bf16(float (&d)[4], const uint32_t (&a)[4],
                                         const uint32_t b0, const uint32_t b1) {
    asm volatile(
        "mma.sync.aligned.m16n8k16.row.col.f32.bf16.bf16.f32 "
        "{%0,%1,%2,%3}, {%4,%5,%6,%7}, {%8,%9}, {%0,%1,%2,%3};"
        : "+f"(d[0]), "+f"(d[1]), "+f"(d[2]), "+f"(d[3])
        : "r"(a[0]), "r"(a[1]), "r"(a[2]), "r"(a[3]), "r"(b0), "r"(b1));
}
__device__ __forceinline__ uint32_t pack_bf16(float x, float y) {
    __nv_bfloat162 t = __floats2bfloat162_rn(x, y);
    return *reinterpret_cast<uint32_t*>(&t);
}
__device__ __forceinline__ uint32_t pack_lo(float x, float y, uint32_t hp) {
    __nv_bfloat162 hh = *reinterpret_cast<__nv_bfloat162*>(&hp);
    float2 hf = __bfloat1622float2(hh);
    __nv_bfloat162 t = __floats2bfloat162_rn(x - hf.x, y - hf.y);
    return *reinterpret_cast<uint32_t*>(&t);
}

// FFMA-only 2^z (no MUFU). z <= ~1 expected; clamped below at -100.
// magic-constant round-to-nearest, degree-5 poly on f in [-0.5,0.5],
// exponent applied via integer bit-add. rel err ~2e-6.
__device__ __forceinline__ float fexp2(float z) {
    z = fmaxf(z, -100.0f);
    const float magic = 12582912.0f;            // 1.5 * 2^23
    const float zc = z + magic;                 // round(z) in mantissa
    const int   n23 = __float_as_int(zc) << 23; // n << 23 (two's complement ok)
    const float f = z - (zc - magic);           // f in [-0.5, 0.5]
    float p = 0.0013333558f;
    p = fmaf(p, f, 0.0096181291f);
    p = fmaf(p, f, 0.0555041087f);
    p = fmaf(p, f, 0.2402265069f);
    p = fmaf(p, f, 0.6931471806f);
    p = fmaf(p, f, 1.0f);
    return __int_as_float(__float_as_int(p) + n23);
}

// ---------------------------------------------------------------------------
// Splits
// ---------------------------------------------------------------------------
__global__ void split_x(const float* __restrict__ src, int n4)
{
    const int i = blockIdx.x * blockDim.x + threadIdx.x;
    if (i >= n4) return;
    float4 v = ((const float4*)src)[i];
    __nv_bfloat162 h01 = __floats2bfloat162_rn(v.x, v.y);
    __nv_bfloat162 h23 = __floats2bfloat162_rn(v.z, v.w);
    float2 f01 = __bfloat1622float2(h01);
    float2 f23 = __bfloat1622float2(h23);
    __nv_bfloat162 l01 = __floats2bfloat162_rn(v.x - f01.x, v.y - f01.y);
    __nv_bfloat162 l23 = __floats2bfloat162_rn(v.z - f23.x, v.w - f23.y);
    uint2 H, L;
    H.x = *reinterpret_cast<uint32_t*>(&h01); H.y = *reinterpret_cast<uint32_t*>(&h23);
    L.x = *reinterpret_cast<uint32_t*>(&l01); L.y = *reinterpret_cast<uint32_t*>(&l23);
    ((uint2*)g_xh)[i] = H;
    ((uint2*)g_xl)[i] = L;
}

__global__ void split_w4(const float* __restrict__ Wq, const float* __restrict__ Wk,
                         const float* __restrict__ Wv, const float* __restrict__ Wo,
                         int n4)
{
    const int i = blockIdx.x * blockDim.x + threadIdx.x;
    if (i >= n4) return;
    const int w = blockIdx.y;
    const float* src = (w == 0) ? Wq : (w == 1) ? Wk : (w == 2) ? Wv : Wo;
    __nv_bfloat16* hi = (w == 0) ? g_wqh : (w == 1) ? g_wkh : (w == 2) ? g_wvh : g_woh;
    __nv_bfloat16* lo = (w == 0) ? g_wql : (w == 1) ? g_wkl : (w == 2) ? g_wvl : g_wol;

    float4 v = ((const float4*)src)[i];
    __nv_bfloat162 h01 = __floats2bfloat162_rn(v.x, v.y);
    __nv_bfloat162 h23 = __floats2bfloat162_rn(v.z, v.w);
    float2 f01 = __bfloat1622float2(h01);
    float2 f23 = __bfloat1622float2(h23);
    __nv_bfloat162 l01 = __floats2bfloat162_rn(v.x - f01.x, v.y - f01.y);
    __nv_bfloat162 l23 = __floats2bfloat162_rn(v.z - f23.x, v.w - f23.y);
    uint2 H, L;
    H.x = *reinterpret_cast<uint32_t*>(&h01); H.y = *reinterpret_cast<uint32_t*>(&h23);
    L.x = *reinterpret_cast<uint32_t*>(&l01); L.y = *reinterpret_cast<uint32_t*>(&l23);
    ((uint2*)hi)[i] = H;
    ((uint2*)lo)[i] = L;
}

// ---------------------------------------------------------------------------
// HMMA mainloop (R9/R11 proven): acc += (Ah+Al)*(Bh+Bl)^T, 3-term split.
// Single buffer; 2 CTAs/SM hide latency (R10: double-buffering regresses).
// ---------------------------------------------------------------------------
constexpr int SMEM_BYTES = 4 * 128 * 80;   // 40960

__device__ __forceinline__ void gemm_mainloop(
    float (&acc)[4][4][4],
    const __nv_bfloat16* __restrict__ Ah, const __nv_bfloat16* __restrict__ Al,
    const __nv_bfloat16* __restrict__ Bh, const __nv_bfloat16* __restrict__ Bl,
    int ldA, int ldB, int K, char* smem)
{
    const int tid  = threadIdx.x;
    const int wid  = tid >> 5, lane = tid & 31;
    const int wm   = wid >> 2, wn = wid & 3;
    const uint32_t sb  = smem_to_u32(smem);
    const uint32_t sAh = sb, sAl = sb + 10240, sBh = sb + 20480, sBl = sb + 30720;

    const int lr = tid >> 2;
    const int lc = (tid & 3) * 8;

    const int arow = wm * 64 + (lane & 15);
    const int acol = (lane >> 4) << 3;
    const uint32_t aoff = (uint32_t)arow * 80 + acol * 2;
    const int brow = wn * 32 + (lane & 7) + ((lane & 16) >> 1);
    const int bcol = lane & 8;
    const uint32_t boff = (uint32_t)brow * 80 + bcol * 2;

    const int nchunks = K >> 5;
    for (int ch = 0; ch < nchunks; ch++) {
        const int k0 = ch * 32;
        #pragma unroll
        for (int it = 0; it < 2; it++) {
            const int r = lr + it * 64;
            const uint32_t so = (uint32_t)r * 80 + lc * 2;
            cp_async16(sAh + so, Ah + (size_t)r * ldA + k0 + lc);
            cp_async16(sAl + so, Al + (size_t)r * ldA + k0 + lc);
            cp_async16(sBh + so, Bh + (size_t)r * ldB + k0 + lc);
            cp_async16(sBl + so, Bl + (size_t)r * ldB + k0 + lc);
        }
        cp_commit();
        cp_wait0();
        __syncthreads();

        #pragma unroll
        for (int ks = 0; ks < 2; ks++) {
            uint32_t ah[4][4], al[4][4];
            uint32_t bh0[4], bh1[4], bl0[4], bl1[4];
            #pragma unroll
            for (int mt = 0; mt < 4; mt++) {
                const uint32_t off = aoff + (uint32_t)mt * 16 * 80 + ks * 32;
                ldsm_x4(ah[mt], sAh + off);
                ldsm_x4(al[mt], sAl + off);
            }
            #pragma unroll
            for (int p = 0; p < 2; p++) {
                const uint32_t off = boff + (uint32_t)p * 16 * 80 + ks * 32;
                uint32_t t[4];
                ldsm_x4(t, sBh + off);
                bh0[2*p] = t[0]; bh1[2*p] = t[1]; bh0[2*p+1] = t[2]; bh1[2*p+1] = t[3];
                ldsm_x4(t, sBl + off);
                bl0[2*p] = t[0]; bl1[2*p] = t[1]; bl0[2*p+1] = t[2]; bl1[2*p+1] = t[3];
            }
            #pragma unroll
            for (int mt = 0; mt < 4; mt++)
                #pragma unroll
                for (int nt = 0; nt < 4; nt++) {
                    mma_bf16(acc[mt][nt], ah[mt], bh0[nt], bh1[nt]);
                    mma_bf16(acc[mt][nt], ah[mt], bl0[nt], bl1[nt]);
                    mma_bf16(acc[mt][nt], al[mt], bh0[nt], bh1[nt]);
                }
        }
        __syncthreads();
    }
}

// ---------------------------------------------------------------------------
// Merged Q/K/V projection: grid (8, 32, 3) = 768 CTAs
// ---------------------------------------------------------------------------
__global__ __launch_bounds__(256)
void proj_qkv(const float* __restrict__ bq, const float* __restrict__ bk,
              const float* __restrict__ bv)
{
    extern __shared__ __align__(16) char smem[];
    const int which = blockIdx.z;
    const int mBase = blockIdx.y * 128;
    const int nBase = blockIdx.x * 128;

    const __nv_bfloat16* wh = (which == 0) ? g_wqh : (which == 1) ? g_wkh : g_wvh;
    const __nv_bfloat16* wl = (which == 0) ? g_wql : (which == 1) ? g_wkl : g_wvl;
    const float* bias       = (which == 0) ? bq    : (which == 1) ? bk    : bv;
    __nv_bfloat16* dh       = (which == 0) ? g_qh  : (which == 1) ? g_kh  : g_vh;
    __nv_bfloat16* dl       = (which == 0) ? g_ql  : (which == 1) ? g_kl  : g_vl;

    float acc[4][4][4];
    #pragma unroll
    for (int i = 0; i < 4; i++)
        #pragma unroll
        for (int j = 0; j < 4; j++)
            #pragma unroll
            for (int e = 0; e < 4; e++) acc[i][j][e] = 0.0f;

    gemm_mainloop(acc,
                  g_xh + (size_t)mBase * Dc, g_xl + (size_t)mBase * Dc,
                  wh + (size_t)nBase * Dc, wl + (size_t)nBase * Dc,
                  Dc, Dc, Dc, smem);

    const int tid  = threadIdx.x;
    const int wid  = tid >> 5, lane = tid & 31;
    const int wm   = wid >> 2, wn = wid & 3;
    const int g    = lane >> 2, tg = lane & 3;

    #pragma unroll
    for (int mt = 0; mt < 4; mt++) {
        const int r0 = mBase + wm * 64 + mt * 16 + g;
        #pragma unroll
        for (int nt = 0; nt < 4; nt++) {
            const int c0 = nBase + wn * 32 + nt * 8 + tg * 2;
            const float b0 = bias[c0], b1 = bias[c0 + 1];
            #pragma unroll
            for (int half = 0; half < 2; half++) {
                const int r = r0 + half * 8;
                const float v0 = acc[mt][nt][half * 2 + 0] + b0;
                const float v1 = acc[mt][nt][half * 2 + 1] + b1;
                const int b  = r >> 11, s = r & (Sc - 1);
                const int h  = c0 >> 6, hd = c0 & (HDc - 1);
                const size_t idx = (((size_t)(b * Hc + h)) * Sc + s) * HDc + hd;
                const uint32_t hp = pack_bf16(v0, v1);
                *(uint32_t*)(dh + idx) = hp;
                *(uint32_t*)(dl + idx) = pack_lo(v0, v1, hp);
            }
        }
    }
}

// ---------------------------------------------------------------------------
// Final O projection: out = AO * Wo^T + bo  (fp32 out)
// ---------------------------------------------------------------------------
__global__ __launch_bounds__(256)
void proj_o(const float* __restrict__ bias, float* __restrict__ outPlain)
{
    extern __shared__ __align__(16) char smem[];
    const int mBase = blockIdx.y * 128;
    const int nBase = blockIdx.x * 128;

    float acc[4][4][4];
    #pragma unroll
    for (int i = 0; i < 4; i++)
        #pragma unroll
        for (int j = 0; j < 4; j++)
            #pragma unroll
            for (int e = 0; e < 4; e++) acc[i][j][e] = 0.0f;

    gemm_mainloop(acc,
                  g_xh + (size_t)mBase * Dc, g_xl + (size_t)mBase * Dc,
                  g_woh + (size_t)nBase * Dc, g_wol + (size_t)nBase * Dc,
                  Dc, Dc, Dc, smem);

    const int tid  = threadIdx.x;
    const int wid  = tid >> 5, lane = tid & 31;
    const int wm   = wid >> 2, wn = wid & 3;
    const int g    = lane >> 2, tg = lane & 3;

    #pragma unroll
    for (int mt = 0; mt < 4; mt++) {
        const int r0 = mBase + wm * 64 + mt * 16 + g;
        #pragma unroll
        for (int nt = 0; nt < 4; nt++) {
            const int c0 = nBase + wn * 32 + nt * 8 + tg * 2;
            const float b0 = bias[c0], b1 = bias[c0 + 1];
            #pragma unroll
            for (int half = 0; half < 2; half++) {
                const int r = r0 + half * 8;
                const float v0 = acc[mt][nt][half * 2 + 0] + b0;
                const float v1 = acc[mt][nt][half * 2 + 1] + b1;
                *(float2*)(outPlain + (size_t)r * Dc + c0) = make_float2(v0, v1);
            }
        }
    }
}

// ---------------------------------------------------------------------------
// Fused flash attention: R11/R12 structure, softmax in 2^x domain with
// FFMA-only fexp2 (no MUFU). Scale/mask fold log2e in.
// ---------------------------------------------------------------------------
constexpr int TS        = 144;
constexpr int QTILE_B   = 128 * TS;                 // 18432
constexpr int KVTILE_B  = 64 * TS;                  // 9216
constexpr int KVSTAGE_B = 4 * KVTILE_B;             // 36864
constexpr int FLASH_SMEM = 2 * QTILE_B + 2 * KVSTAGE_B;   // 110592

__global__ __launch_bounds__(256, 2)
void flash_kernel(const float* __restrict__ mask)
{
    extern __shared__ __align__(16) char smem[];
    const uint32_t sb = smem_to_u32(smem);
    const int tid = threadIdx.x, wid = tid >> 5, lane = tid & 31;
    const int g = lane >> 2, tg = lane & 3;
    const int qBase = blockIdx.x * 128;
    const int bh = blockIdx.y;
    const int b = bh >> 4, h = bh & (Hc - 1);

    const size_t bhOff = (size_t)bh * Sc * HDc;
    const __nv_bfloat16* __restrict__ Qh = g_qh + bhOff + (size_t)qBase * HDc;
    const __nv_bfloat16* __restrict__ Ql = g_ql + bhOff + (size_t)qBase * HDc;
    const __nv_bfloat16* __restrict__ Kh = g_kh + bhOff;
    const __nv_bfloat16* __restrict__ Kl = g_kl + bhOff;
    const __nv_bfloat16* __restrict__ Vh = g_vh + bhOff;
    const __nv_bfloat16* __restrict__ Vl = g_vl + bhOff;

    const uint32_t sQH = sb, sQL = sb + QTILE_B;

    #pragma unroll
    for (int i = 0; i < 4; i++) {
        const int c = tid + i * 256;
        const int r = c >> 3, cc = c & 7;
        const uint32_t so = (uint32_t)r * TS + cc * 16;
        cp_async16(sQH + so, Qh + (size_t)r * HDc + cc * 8);
        cp_async16(sQL + so, Ql + (size_t)r * HDc + cc * 8);
    }
    cp_commit();

    auto loadKV = [&](int kb, int st) {
        const uint32_t bufB = sb + 2 * QTILE_B + (uint32_t)st * KVSTAGE_B;
        const size_t base = (size_t)kb * 64 * HDc;
        #pragma unroll
        for (int i = 0; i < 2; i++) {
            const int c = tid + i * 256;
            const int r = c >> 3, cc = c & 7;
            const uint32_t so = (uint32_t)r * TS + cc * 16;
            const size_t go = base + (size_t)r * HDc + cc * 8;
            cp_async16(bufB                + so, Kh + go);
            cp_async16(bufB +     KVTILE_B + so, Kl + go);
            cp_async16(bufB + 2 * KVTILE_B + so, Vh + go);
            cp_async16(bufB + 3 * KVTILE_B + so, Vl + go);
        }
        cp_commit();
    };
    loadKV(0, 0);
    cp_wait0();
    __syncthreads();

    uint32_t qah[4][4], qal[4][4];
    {
        const uint32_t arow = (uint32_t)(wid * 16 + (lane & 15));
        const uint32_t acolb = (uint32_t)((lane >> 4) * 16);
        #pragma unroll
        for (int kk = 0; kk < 4; kk++) {
            const uint32_t off = arow * TS + kk * 32 + acolb;
            ldsm_x4(qah[kk], sQH + off);
            ldsm_x4(qal[kk], sQL + off);
        }
    }

    float o[8][4];
    #pragma unroll
    for (int i = 0; i < 8; i++)
        #pragma unroll
        for (int e = 0; e < 4; e++) o[i][e] = 0.0f;
    float mrun0 = -3e38f, mrun1 = -3e38f, l0 = 0.0f, l1 = 0.0f;

    const float* __restrict__ M0 =
        mask + ((size_t)b * Sc + qBase + wid * 16 + g) * Sc;

    const uint32_t brow = (uint32_t)((lane & 7) + ((lane & 16) >> 1));
    const uint32_t bcolb = (uint32_t)((lane & 8) << 1);
    const uint32_t vrow = (uint32_t)((lane & 7) + (lane & 8));
    const uint32_t vcolb = (uint32_t)(lane & 16);

    // 2^x-domain softmax constants: exp(s*0.125 + m) = 2^(s*SC + m*L2E)
    constexpr float SC  = 0.125f * 1.4426950409f;   // 0.18033688...
    constexpr float L2E = 1.4426950409f;

    for (int kb = 0; kb < 32; kb++) {
        if (kb + 1 < 32) { loadKV(kb + 1, (kb + 1) & 1); cp_wait1(); }
        else             { cp_wait0(); }
        __syncthreads();

        const uint32_t bufB = sb + 2 * QTILE_B + (uint32_t)(kb & 1) * KVSTAGE_B;
        const uint32_t sKH = bufB, sKL = bufB + KVTILE_B;
        const uint32_t sVH = bufB + 2 * KVTILE_B, sVL = bufB + 3 * KVTILE_B;

        float s[8][4];
        #pragma unroll
        for (int nt = 0; nt < 8; nt++)
            #pragma unroll
            for (int e = 0; e < 4; e++) s[nt][e] = 0.0f;

        #pragma unroll
        for (int p = 0; p < 4; p++) {
            #pragma unroll
            for (int kk = 0; kk < 4; kk++) {
                uint32_t tbh[4], tbl[4];
                const uint32_t off = (uint32_t)(16 * p + brow) * TS + kk * 32 + bcolb;
                ldsm_x4(tbh, sKH + off);
                ldsm_x4(tbl, sKL + off);
                mma_bf16(s[2*p],   qah[kk], tbh[0], tbh[1]);
                mma_bf16(s[2*p],   qah[kk], tbl[0], tbl[1]);
                mma_bf16(s[2*p],   qal[kk], tbh[0], tbh[1]);
                mma_bf16(s[2*p+1], qah[kk], tbh[2], tbh[3]);
                mma_bf16(s[2*p+1], qah[kk], tbl[2], tbl[3]);
                mma_bf16(s[2*p+1], qal[kk], tbh[2], tbh[3]);
            }
        }

        // scale + mask (2^x domain) + row max (rows g and g+8, warp-local)
        const float* Mk0 = M0 + (size_t)kb * 64;
        float mx0 = -3e38f, mx1 = -3e38f;
        #pragma unroll
        for (int nt = 0; nt < 8; nt++) {
            const int col = nt * 8 + tg * 2;
            const float2 a = *(const float2*)(Mk0 + col);
            const float2 c = *(const float2*)(Mk0 + 8 * (size_t)Sc + col);
            s[nt][0] = fmaf(s[nt][0], SC, a.x * L2E);
            s[nt][1] = fmaf(s[nt][1], SC, a.y * L2E);
            s[nt][2] = fmaf(s[nt][2], SC, c.x * L2E);
            s[nt][3] = fmaf(s[nt][3], SC, c.y * L2E);
            mx0 = fmaxf(mx0, fmaxf(s[nt][0], s[nt][1]));
            mx1 = fmaxf(mx1, fmaxf(s[nt][2], s[nt][3]));
        }
        #pragma unroll
        for (int d = 1; d < 4; d <<= 1) {
            mx0 = fmaxf(mx0, __shfl_xor_sync(0xffffffffu, mx0, d));
            mx1 = fmaxf(mx1, __shfl_xor_sync(0xffffffffu, mx1, d));
        }
        const float mn0 = fmaxf(mrun0, mx0), mn1 = fmaxf(mrun1, mx1);
        const float c0 = fexp2(mrun0 - mn0), c1 = fexp2(mrun1 - mn1);
        mrun0 = mn0; mrun1 = mn1;
        #pragma unroll
        for (int nt = 0; nt < 8; nt++) {
            o[nt][0] *= c0; o[nt][1] *= c0;
            o[nt][2] *= c1; o[nt][3] *= c1;
        }

        float rs0 = 0.0f, rs1 = 0.0f;
        #pragma unroll
        for (int j = 0; j < 4; j++) {
            const float p0 = fexp2(s[2*j][0]   - mn0), p1 = fexp2(s[2*j][1]   - mn0);
            const float p2 = fexp2(s[2*j][2]   - mn1), p3 = fexp2(s[2*j][3]   - mn1);
            const float p4 = fexp2(s[2*j+1][0] - mn0), p5 = fexp2(s[2*j+1][1] - mn0);
            const float p6 = fexp2(s[2*j+1][2] - mn1), p7 = fexp2(s[2*j+1][3] - mn1);
            rs0 += (p0 + p1) + (p4 + p5);
            rs1 += (p2 + p3) + (p6 + p7);

            uint32_t ah_[4], al_[4];
            ah_[0] = pack_bf16(p0, p1); ah_[1] = pack_bf16(p2, p3);
            ah_[2] = pack_bf16(p4, p5); ah_[3] = pack_bf16(p6, p7);
            al_[0] = pack_lo(p0, p1, ah_[0]); al_[1] = pack_lo(p2, p3, ah_[1]);
            al_[2] = pack_lo(p4, p5, ah_[2]); al_[3] = pack_lo(p6, p7, ah_[3]);

            #pragma unroll
            for (int q = 0; q < 4; q++) {
                uint32_t tvh[4], tvl[4];
                const uint32_t off = (uint32_t)(16 * j + vrow) * TS + q * 32 + vcolb;
                ldsm_x4_trans(tvh, sVH + off);
                ldsm_x4_trans(tvl, sVL + off);
                mma_bf16(o[2*q],   ah_, tvh[0], tvh[1]);
                mma_bf16(o[2*q],   al_, tvh[0], tvh[1]);
                mma_bf16(o[2*q],   ah_, tvl[0], tvl[1]);
                mma_bf16(o[2*q+1], ah_, tvh[2], tvh[3]);
                mma_bf16(o[2*q+1], al_, tvh[2], tvh[3]);
                mma_bf16(o[2*q+1], ah_, tvl[2], tvl[3]);
            }
        }
        #pragma unroll
        for (int d = 1; d < 4; d <<= 1) {
            rs0 += __shfl_xor_sync(0xffffffffu, rs0, d);
            rs1 += __shfl_xor_sync(0xffffffffu, rs1, d);
        }
        l0 = l0 * c0 + rs0;
        l1 = l1 * c1 + rs1;

        __syncthreads();
    }

    const float i0 = 1.0f / l0, i1 = 1.0f / l1;
    const int row0 = b * Sc + qBase + wid * 16 + g;
    #pragma unroll
    for (int nt = 0; nt < 8; nt++) {
        const int col = h * HDc + nt * 8 + tg * 2;
        const float v0 = o[nt][0] * i0, v1 = o[nt][1] * i0;
        const float v2 = o[nt][2] * i1, v3 = o[nt][3] * i1;
        const uint32_t h0 = pack_bf16(v0, v1), h1 = pack_bf16(v2, v3);
        *(uint32_t*)(g_xh + (size_t)row0 * Dc + col)       = h0;
        *(uint32_t*)(g_xl + (size_t)row0 * Dc + col)       = pack_lo(v0, v1, h0);
        *(uint32_t*)(g_xh + (size_t)(row0 + 8) * Dc + col) = h1;
        *(uint32_t*)(g_xl + (size_t)(row0 + 8) * Dc + col) = pack_lo(v2, v3, h1);
    }
}

// ---------------------------------------------------------------------------
// Launch: 5 kernels
// ---------------------------------------------------------------------------
extern "C" void kernel_launch(void* const* d_in, const int* in_sizes, int n_in,
                              void* d_out, int out_size)
{
    (void)in_sizes; (void)n_in; (void)out_size;

    const float* hs   = (const float*)d_in[0];
    const float* mask = (const float*)d_in[1];
    const float* Wq   = (const float*)d_in[2];
    const float* bq   = (const float*)d_in[3];
    const float* Wk   = (const float*)d_in[4];
    const float* bk   = (const float*)d_in[5];
    const float* Wv   = (const float*)d_in[6];
    const float* bv   = (const float*)d_in[7];
    const float* Wo   = (const float*)d_in[8];
    const float* bo   = (const float*)d_in[9];
    float* out = (float*)d_out;

    static bool attrDone = false;
    if (!attrDone) {
        cudaFuncSetAttribute(flash_kernel,
                             cudaFuncAttributeMaxDynamicSharedMemorySize, FLASH_SMEM);
        attrDone = true;
    }

    const int nX4 = Mc * Dc / 4;   // 1,048,576
    const int nW4 = Dc * Dc / 4;   // 262,144
    const dim3 gGemm(Dc / 128, Mc / 128);        // (8, 32)
    const dim3 gQKV(Dc / 128, Mc / 128, 3);      // (8, 32, 3)
    const dim3 gFlash(Sc / 128, Bc * Hc);        // (16, 32)
    const dim3 gW4((nW4 + 255) / 256, 4);

    split_x<<<(nX4 + 255) / 256, 256>>>(hs, nX4);
    split_w4<<<gW4, 256>>>(Wq, Wk, Wv, Wo, nW4);

    proj_qkv<<<gQKV, 256, SMEM_BYTES>>>(bq, bk, bv);

    flash_kernel<<<gFlash, 256, FLASH_SMEM>>>(mask);

    proj_o<<<gGemm, 256, SMEM_BYTES>>>(bo, out);
}

// round 14
// speedup vs baseline: 1.0460x; 1.0460x over previous
#include <cuda_runtime.h>
#include <cuda_bf16.h>
#include <cstdint>
#include <cstddef>

// Problem constants: B=2, S=2048, D=1024, H=16, HD=64
constexpr int Bc  = 2;
constexpr int Sc  = 2048;
constexpr int Dc  = 1024;
constexpr int Hc  = 16;
constexpr int HDc = 64;
constexpr int Mc  = Bc * Sc;   // 4096

// ---------------------------------------------------------------------------
// Static device scratch (all bf16 hi/lo pairs)
// ---------------------------------------------------------------------------
__device__ __nv_bfloat16 g_xh[(size_t)Mc * Dc];   // activations hi (reused for attn-out)
__device__ __nv_bfloat16 g_xl[(size_t)Mc * Dc];   // activations lo

__device__ __nv_bfloat16 g_wqh[(size_t)Dc * Dc];
__device__ __nv_bfloat16 g_wql[(size_t)Dc * Dc];
__device__ __nv_bfloat16 g_wkh[(size_t)Dc * Dc];
__device__ __nv_bfloat16 g_wkl[(size_t)Dc * Dc];
__device__ __nv_bfloat16 g_wvh[(size_t)Dc * Dc];
__device__ __nv_bfloat16 g_wvl[(size_t)Dc * Dc];
__device__ __nv_bfloat16 g_woh[(size_t)Dc * Dc];
__device__ __nv_bfloat16 g_wol[(size_t)Dc * Dc];

__device__ __nv_bfloat16 g_qh[(size_t)Bc * Hc * Sc * HDc];
__device__ __nv_bfloat16 g_ql[(size_t)Bc * Hc * Sc * HDc];
__device__ __nv_bfloat16 g_kh[(size_t)Bc * Hc * Sc * HDc];
__device__ __nv_bfloat16 g_kl[(size_t)Bc * Hc * Sc * HDc];
__device__ __nv_bfloat16 g_vh[(size_t)Bc * Hc * Sc * HDc];
__device__ __nv_bfloat16 g_vl[(size_t)Bc * Hc * Sc * HDc];

// ---------------------------------------------------------------------------
// PTX helpers (baseline ISA only — compute_103 safe)
// ---------------------------------------------------------------------------
__device__ __forceinline__ uint32_t smem_to_u32(const void* p) {
    uint32_t a;
    asm("{ .reg .u64 t; cvta.to.shared.u64 t, %1; cvt.u32.u64 %0, t; }"
        : "=r"(a) : "l"(p));
    return a;
}
__device__ __forceinline__ void cp_async16(uint32_t dst, const void* src) {
    asm volatile("cp.async.cg.shared.global [%0], [%1], 16;"
                 :: "r"(dst), "l"(src) : "memory");
}
__device__ __forceinline__ void cp_commit() {
    asm volatile("cp.async.commit_group;" ::: "memory");
}
__device__ __forceinline__ void cp_wait0() {
    asm volatile("cp.async.wait_group 0;" ::: "memory");
}
__device__ __forceinline__ void cp_wait1() {
    asm volatile("cp.async.wait_group 1;" ::: "memory");
}
__device__ __forceinline__ void ldsm_x4(uint32_t (&r)[4], uint32_t addr) {
    asm volatile("ldmatrix.sync.aligned.m8n8.x4.shared.b16 {%0,%1,%2,%3}, [%4];"
                 : "=r"(r[0]), "=r"(r[1]), "=r"(r[2]), "=r"(r[3]) : "r"(addr));
}
__device__ __forceinline__ void ldsm_x4_trans(uint32_t (&r)[4], uint32_t addr) {
    asm volatile("ldmatrix.sync.aligned.m8n8.x4.trans.shared.b16 {%0,%1,%2,%3}, [%4];"
                 : "=r"(r[0]), "=r"(r[1]), "=r"(r[2]), "=r"(r[3]) : "r"(addr));
}
__device__ __forceinline__ void mma_bf16(float (&d)[4], const uint32_t (&a)[4],
                                         const uint32_t b0, const uint32_t b1) {
    asm volatile(
        "mma.sync.aligned.m16n8k16.row.col.f32.bf16.bf16.f32 "
        "{%0,%1,%2,%3}, {%4,%5,%6,%7}, {%8,%9}, {%0,%1,%2,%3};"
        : "+f"(d[0]), "+f"(d[1]), "+f"(d[2]), "+f"(d[3])
        : "r"(a[0]), "r"(a[1]), "r"(a[2]), "r"(a[3]), "r"(b0), "r"(b1));
}
__device__ __forceinline__ uint32_t pack_bf16(float x, float y) {
    __nv_bfloat162 t = __floats2bfloat162_rn(x, y);
    return *reinterpret_cast<uint32_t*>(&t);
}
__device__ __forceinline__ uint32_t pack_lo(float x, float y, uint32_t hp) {
    __nv_bfloat162 hh = *reinterpret_cast<__nv_bfloat162*>(&hp);
    float2 hf = __bfloat1622float2(hh);
    __nv_bfloat162 t = __floats2bfloat162_rn(x - hf.x, y - hf.y);
    return *reinterpret_cast<uint32_t*>(&t);
}

// ---------------------------------------------------------------------------
// Splits
// ---------------------------------------------------------------------------
__global__ void split_x(const float* __restrict__ src, int n4)
{
    const int i = blockIdx.x * blockDim.x + threadIdx.x;
    if (i >= n4) return;
    float4 v = ((const float4*)src)[i];
    __nv_bfloat162 h01 = __floats2bfloat162_rn(v.x, v.y);
    __nv_bfloat162 h23 = __floats2bfloat162_rn(v.z, v.w);
    float2 f01 = __bfloat1622float2(h01);
    float2 f23 = __bfloat1622float2(h23);
    __nv_bfloat162 l01 = __floats2bfloat162_rn(v.x - f01.x, v.y - f01.y);
    __nv_bfloat162 l23 = __floats2bfloat162_rn(v.z - f23.x, v.w - f23.y);
    uint2 H, L;
    H.x = *reinterpret_cast<uint32_t*>(&h01); H.y = *reinterpret_cast<uint32_t*>(&h23);
    L.x = *reinterpret_cast<uint32_t*>(&l01); L.y = *reinterpret_cast<uint32_t*>(&l23);
    ((uint2*)g_xh)[i] = H;
    ((uint2*)g_xl)[i] = L;
}

__global__ void split_w4(const float* __restrict__ Wq, const float* __restrict__ Wk,
                         const float* __restrict__ Wv, const float* __restrict__ Wo,
                         int n4)
{
    const int i = blockIdx.x * blockDim.x + threadIdx.x;
    if (i >= n4) return;
    const int w = blockIdx.y;
    const float* src = (w == 0) ? Wq : (w == 1) ? Wk : (w == 2) ? Wv : Wo;
    __nv_bfloat16* hi = (w == 0) ? g_wqh : (w == 1) ? g_wkh : (w == 2) ? g_wvh : g_woh;
    __nv_bfloat16* lo = (w == 0) ? g_wql : (w == 1) ? g_wkl : (w == 2) ? g_wvl : g_wol;

    float4 v = ((const float4*)src)[i];
    __nv_bfloat162 h01 = __floats2bfloat162_rn(v.x, v.y);
    __nv_bfloat162 h23 = __floats2bfloat162_rn(v.z, v.w);
    float2 f01 = __bfloat1622float2(h01);
    float2 f23 = __bfloat1622float2(h23);
    __nv_bfloat162 l01 = __floats2bfloat162_rn(v.x - f01.x, v.y - f01.y);
    __nv_bfloat162 l23 = __floats2bfloat162_rn(v.z - f23.x, v.w - f23.y);
    uint2 H, L;
    H.x = *reinterpret_cast<uint32_t*>(&h01); H.y = *reinterpret_cast<uint32_t*>(&h23);
    L.x = *reinterpret_cast<uint32_t*>(&l01); L.y = *reinterpret_cast<uint32_t*>(&l23);
    ((uint2*)hi)[i] = H;
    ((uint2*)lo)[i] = L;
}

// ---------------------------------------------------------------------------
// HMMA mainloop: acc += (Ah+Al)*(Bh+Bl)^T, 3-term split.
// R14 change: TERM-MAJOR MMA ordering — all 16 accumulators are touched per
// term before any accumulator repeats (same-acc issue distance 16, hides
// HMMA result latency). Fragments/registers unchanged.
// ---------------------------------------------------------------------------
constexpr int SMEM_BYTES = 4 * 128 * 80;   // 40960

__device__ __forceinline__ void gemm_mainloop(
    float (&acc)[4][4][4],
    const __nv_bfloat16* __restrict__ Ah, const __nv_bfloat16* __restrict__ Al,
    const __nv_bfloat16* __restrict__ Bh, const __nv_bfloat16* __restrict__ Bl,
    int ldA, int ldB, int K, char* smem)
{
    const int tid  = threadIdx.x;
    const int wid  = tid >> 5, lane = tid & 31;
    const int wm   = wid >> 2, wn = wid & 3;
    const uint32_t sb  = smem_to_u32(smem);
    const uint32_t sAh = sb, sAl = sb + 10240, sBh = sb + 20480, sBl = sb + 30720;

    const int lr = tid >> 2;
    const int lc = (tid & 3) * 8;

    const int arow = wm * 64 + (lane & 15);
    const int acol = (lane >> 4) << 3;
    const uint32_t aoff = (uint32_t)arow * 80 + acol * 2;
    const int brow = wn * 32 + (lane & 7) + ((lane & 16) >> 1);
    const int bcol = lane & 8;
    const uint32_t boff = (uint32_t)brow * 80 + bcol * 2;

    const int nchunks = K >> 5;
    for (int ch = 0; ch < nchunks; ch++) {
        const int k0 = ch * 32;
        #pragma unroll
        for (int it = 0; it < 2; it++) {
            const int r = lr + it * 64;
            const uint32_t so = (uint32_t)r * 80 + lc * 2;
            cp_async16(sAh + so, Ah + (size_t)r * ldA + k0 + lc);
            cp_async16(sAl + so, Al + (size_t)r * ldA + k0 + lc);
            cp_async16(sBh + so, Bh + (size_t)r * ldB + k0 + lc);
            cp_async16(sBl + so, Bl + (size_t)r * ldB + k0 + lc);
        }
        cp_commit();
        cp_wait0();
        __syncthreads();

        #pragma unroll
        for (int ks = 0; ks < 2; ks++) {
            uint32_t ah[4][4], al[4][4];
            uint32_t bh0[4], bh1[4], bl0[4], bl1[4];
            #pragma unroll
            for (int mt = 0; mt < 4; mt++) {
                const uint32_t off = aoff + (uint32_t)mt * 16 * 80 + ks * 32;
                ldsm_x4(ah[mt], sAh + off);
                ldsm_x4(al[mt], sAl + off);
            }
            #pragma unroll
            for (int p = 0; p < 2; p++) {
                const uint32_t off = boff + (uint32_t)p * 16 * 80 + ks * 32;
                uint32_t t[4];
                ldsm_x4(t, sBh + off);
                bh0[2*p] = t[0]; bh1[2*p] = t[1]; bh0[2*p+1] = t[2]; bh1[2*p+1] = t[3];
                ldsm_x4(t, sBl + off);
                bl0[2*p] = t[0]; bl1[2*p] = t[1]; bl0[2*p+1] = t[2]; bl1[2*p+1] = t[3];
            }
            // term-major: same accumulator revisited only every 16 MMAs
            #pragma unroll
            for (int mt = 0; mt < 4; mt++)
                #pragma unroll
                for (int nt = 0; nt < 4; nt++)
                    mma_bf16(acc[mt][nt], ah[mt], bh0[nt], bh1[nt]);
            #pragma unroll
            for (int mt = 0; mt < 4; mt++)
                #pragma unroll
                for (int nt = 0; nt < 4; nt++)
                    mma_bf16(acc[mt][nt], ah[mt], bl0[nt], bl1[nt]);
            #pragma unroll
            for (int mt = 0; mt < 4; mt++)
                #pragma unroll
                for (int nt = 0; nt < 4; nt++)
                    mma_bf16(acc[mt][nt], al[mt], bh0[nt], bh1[nt]);
        }
        __syncthreads();
    }
}

// ---------------------------------------------------------------------------
// Merged Q/K/V projection: grid (8, 32, 3) = 768 CTAs
// ---------------------------------------------------------------------------
__global__ __launch_bounds__(256)
void proj_qkv(const float* __restrict__ bq, const float* __restrict__ bk,
              const float* __restrict__ bv)
{
    extern __shared__ __align__(16) char smem[];
    const int which = blockIdx.z;
    const int mBase = blockIdx.y * 128;
    const int nBase = blockIdx.x * 128;

    const __nv_bfloat16* wh = (which == 0) ? g_wqh : (which == 1) ? g_wkh : g_wvh;
    const __nv_bfloat16* wl = (which == 0) ? g_wql : (which == 1) ? g_wkl : g_wvl;
    const float* bias       = (which == 0) ? bq    : (which == 1) ? bk    : bv;
    __nv_bfloat16* dh       = (which == 0) ? g_qh  : (which == 1) ? g_kh  : g_vh;
    __nv_bfloat16* dl       = (which == 0) ? g_ql  : (which == 1) ? g_kl  : g_vl;

    float acc[4][4][4];
    #pragma unroll
    for (int i = 0; i < 4; i++)
        #pragma unroll
        for (int j = 0; j < 4; j++)
            #pragma unroll
            for (int e = 0; e < 4; e++) acc[i][j][e] = 0.0f;

    gemm_mainloop(acc,
                  g_xh + (size_t)mBase * Dc, g_xl + (size_t)mBase * Dc,
                  wh + (size_t)nBase * Dc, wl + (size_t)nBase * Dc,
                  Dc, Dc, Dc, smem);

    const int tid  = threadIdx.x;
    const int wid  = tid >> 5, lane = tid & 31;
    const int wm   = wid >> 2, wn = wid & 3;
    const int g    = lane >> 2, tg = lane & 3;

    #pragma unroll
    for (int mt = 0; mt < 4; mt++) {
        const int r0 = mBase + wm * 64 + mt * 16 + g;
        #pragma unroll
        for (int nt = 0; nt < 4; nt++) {
            const int c0 = nBase + wn * 32 + nt * 8 + tg * 2;
            const float b0 = bias[c0], b1 = bias[c0 + 1];
            #pragma unroll
            for (int half = 0; half < 2; half++) {
                const int r = r0 + half * 8;
                const float v0 = acc[mt][nt][half * 2 + 0] + b0;
                const float v1 = acc[mt][nt][half * 2 + 1] + b1;
                const int b  = r >> 11, s = r & (Sc - 1);
                const int h  = c0 >> 6, hd = c0 & (HDc - 1);
                const size_t idx = (((size_t)(b * Hc + h)) * Sc + s) * HDc + hd;
                const uint32_t hp = pack_bf16(v0, v1);
                *(uint32_t*)(dh + idx) = hp;
                *(uint32_t*)(dl + idx) = pack_lo(v0, v1, hp);
            }
        }
    }
}

// ---------------------------------------------------------------------------
// Final O projection: out = AO * Wo^T + bo  (fp32 out)
// ---------------------------------------------------------------------------
__global__ __launch_bounds__(256)
void proj_o(const float* __restrict__ bias, float* __restrict__ outPlain)
{
    extern __shared__ __align__(16) char smem[];
    const int mBase = blockIdx.y * 128;
    const int nBase = blockIdx.x * 128;

    float acc[4][4][4];
    #pragma unroll
    for (int i = 0; i < 4; i++)
        #pragma unroll
        for (int j = 0; j < 4; j++)
            #pragma unroll
            for (int e = 0; e < 4; e++) acc[i][j][e] = 0.0f;

    gemm_mainloop(acc,
                  g_xh + (size_t)mBase * Dc, g_xl + (size_t)mBase * Dc,
                  g_woh + (size_t)nBase * Dc, g_wol + (size_t)nBase * Dc,
                  Dc, Dc, Dc, smem);

    const int tid  = threadIdx.x;
    const int wid  = tid >> 5, lane = tid & 31;
    const int wm   = wid >> 2, wn = wid & 3;
    const int g    = lane >> 2, tg = lane & 3;

    #pragma unroll
    for (int mt = 0; mt < 4; mt++) {
        const int r0 = mBase + wm * 64 + mt * 16 + g;
        #pragma unroll
        for (int nt = 0; nt < 4; nt++) {
            const int c0 = nBase + wn * 32 + nt * 8 + tg * 2;
            const float b0 = bias[c0], b1 = bias[c0 + 1];
            #pragma unroll
            for (int half = 0; half < 2; half++) {
                const int r = r0 + half * 8;
                const float v0 = acc[mt][nt][half * 2 + 0] + b0;
                const float v1 = acc[mt][nt][half * 2 + 1] + b1;
                *(float2*)(outPlain + (size_t)r * Dc + c0) = make_float2(v0, v1);
            }
        }
    }
}

// ---------------------------------------------------------------------------
// Fused flash attention: R12 structure (__expf softmax), with MMA issue
// reordered so the two accumulators per fragment-group alternate
// (same-acc distance 2 instead of back-to-back 3-chains).
// ---------------------------------------------------------------------------
constexpr int TS        = 144;
constexpr int QTILE_B   = 128 * TS;                 // 18432
constexpr int KVTILE_B  = 64 * TS;                  // 9216
constexpr int KVSTAGE_B = 4 * KVTILE_B;             // 36864
constexpr int FLASH_SMEM = 2 * QTILE_B + 2 * KVSTAGE_B;   // 110592

__global__ __launch_bounds__(256, 2)
void flash_kernel(const float* __restrict__ mask)
{
    extern __shared__ __align__(16) char smem[];
    const uint32_t sb = smem_to_u32(smem);
    const int tid = threadIdx.x, wid = tid >> 5, lane = tid & 31;
    const int g = lane >> 2, tg = lane & 3;
    const int qBase = blockIdx.x * 128;
    const int bh = blockIdx.y;
    const int b = bh >> 4, h = bh & (Hc - 1);

    const size_t bhOff = (size_t)bh * Sc * HDc;
    const __nv_bfloat16* __restrict__ Qh = g_qh + bhOff + (size_t)qBase * HDc;
    const __nv_bfloat16* __restrict__ Ql = g_ql + bhOff + (size_t)qBase * HDc;
    const __nv_bfloat16* __restrict__ Kh = g_kh + bhOff;
    const __nv_bfloat16* __restrict__ Kl = g_kl + bhOff;
    const __nv_bfloat16* __restrict__ Vh = g_vh + bhOff;
    const __nv_bfloat16* __restrict__ Vl = g_vl + bhOff;

    const uint32_t sQH = sb, sQL = sb + QTILE_B;

    #pragma unroll
    for (int i = 0; i < 4; i++) {
        const int c = tid + i * 256;
        const int r = c >> 3, cc = c & 7;
        const uint32_t so = (uint32_t)r * TS + cc * 16;
        cp_async16(sQH + so, Qh + (size_t)r * HDc + cc * 8);
        cp_async16(sQL + so, Ql + (size_t)r * HDc + cc * 8);
    }
    cp_commit();

    auto loadKV = [&](int kb, int st) {
        const uint32_t bufB = sb + 2 * QTILE_B + (uint32_t)st * KVSTAGE_B;
        const size_t base = (size_t)kb * 64 * HDc;
        #pragma unroll
        for (int i = 0; i < 2; i++) {
            const int c = tid + i * 256;
            const int r = c >> 3, cc = c & 7;
            const uint32_t so = (uint32_t)r * TS + cc * 16;
            const size_t go = base + (size_t)r * HDc + cc * 8;
            cp_async16(bufB                + so, Kh + go);
            cp_async16(bufB +     KVTILE_B + so, Kl + go);
            cp_async16(bufB + 2 * KVTILE_B + so, Vh + go);
            cp_async16(bufB + 3 * KVTILE_B + so, Vl + go);
        }
        cp_commit();
    };
    loadKV(0, 0);
    cp_wait0();
    __syncthreads();

    uint32_t qah[4][4], qal[4][4];
    {
        const uint32_t arow = (uint32_t)(wid * 16 + (lane & 15));
        const uint32_t acolb = (uint32_t)((lane >> 4) * 16);
        #pragma unroll
        for (int kk = 0; kk < 4; kk++) {
            const uint32_t off = arow * TS + kk * 32 + acolb;
            ldsm_x4(qah[kk], sQH + off);
            ldsm_x4(qal[kk], sQL + off);
        }
    }

    float o[8][4];
    #pragma unroll
    for (int i = 0; i < 8; i++)
        #pragma unroll
        for (int e = 0; e < 4; e++) o[i][e] = 0.0f;
    float mrun0 = -3e38f, mrun1 = -3e38f, l0 = 0.0f, l1 = 0.0f;

    const float* __restrict__ M0 =
        mask + ((size_t)b * Sc + qBase + wid * 16 + g) * Sc;

    const uint32_t brow = (uint32_t)((lane & 7) + ((lane & 16) >> 1));
    const uint32_t bcolb = (uint32_t)((lane & 8) << 1);
    const uint32_t vrow = (uint32_t)((lane & 7) + (lane & 8));
    const uint32_t vcolb = (uint32_t)(lane & 16);

    for (int kb = 0; kb < 32; kb++) {
        if (kb + 1 < 32) { loadKV(kb + 1, (kb + 1) & 1); cp_wait1(); }
        else             { cp_wait0(); }
        __syncthreads();

        const uint32_t bufB = sb + 2 * QTILE_B + (uint32_t)(kb & 1) * KVSTAGE_B;
        const uint32_t sKH = bufB, sKL = bufB + KVTILE_B;
        const uint32_t sVH = bufB + 2 * KVTILE_B, sVL = bufB + 3 * KVTILE_B;

        float s[8][4];
        #pragma unroll
        for (int nt = 0; nt < 8; nt++)
            #pragma unroll
            for (int e = 0; e < 4; e++) s[nt][e] = 0.0f;

        #pragma unroll
        for (int p = 0; p < 4; p++) {
            #pragma unroll
            for (int kk = 0; kk < 4; kk++) {
                uint32_t tbh[4], tbl[4];
                const uint32_t off = (uint32_t)(16 * p + brow) * TS + kk * 32 + bcolb;
                ldsm_x4(tbh, sKH + off);
                ldsm_x4(tbl, sKL + off);
                // alternate accumulators: same-acc distance 2
                mma_bf16(s[2*p],   qah[kk], tbh[0], tbh[1]);
                mma_bf16(s[2*p+1], qah[kk], tbh[2], tbh[3]);
                mma_bf16(s[2*p],   qah[kk], tbl[0], tbl[1]);
                mma_bf16(s[2*p+1], qah[kk], tbl[2], tbl[3]);
                mma_bf16(s[2*p],   qal[kk], tbh[0], tbh[1]);
                mma_bf16(s[2*p+1], qal[kk], tbh[2], tbh[3]);
            }
        }

        const float* Mk0 = M0 + (size_t)kb * 64;
        float mx0 = -3e38f, mx1 = -3e38f;
        #pragma unroll
        for (int nt = 0; nt < 8; nt++) {
            const int col = nt * 8 + tg * 2;
            const float2 a = *(const float2*)(Mk0 + col);
            const float2 c = *(const float2*)(Mk0 + 8 * (size_t)Sc + col);
            s[nt][0] = fmaf(s[nt][0], 0.125f, a.x);
            s[nt][1] = fmaf(s[nt][1], 0.125f, a.y);
            s[nt][2] = fmaf(s[nt][2], 0.125f, c.x);
            s[nt][3] = fmaf(s[nt][3], 0.125f, c.y);
            mx0 = fmaxf(mx0, fmaxf(s[nt][0], s[nt][1]));
            mx1 = fmaxf(mx1, fmaxf(s[nt][2], s[nt][3]));
        }
        #pragma unroll
        for (int d = 1; d < 4; d <<= 1) {
            mx0 = fmaxf(mx0, __shfl_xor_sync(0xffffffffu, mx0, d));
            mx1 = fmaxf(mx1, __shfl_xor_sync(0xffffffffu, mx1, d));
        }
        const float mn0 = fmaxf(mrun0, mx0), mn1 = fmaxf(mrun1, mx1);
        const float c0 = __expf(mrun0 - mn0), c1 = __expf(mrun1 - mn1);
        mrun0 = mn0; mrun1 = mn1;
        #pragma unroll
        for (int nt = 0; nt < 8; nt++) {
            o[nt][0] *= c0; o[nt][1] *= c0;
            o[nt][2] *= c1; o[nt][3] *= c1;
        }

        float rs0 = 0.0f, rs1 = 0.0f;
        #pragma unroll
        for (int j = 0; j < 4; j++) {
            const float p0 = __expf(s[2*j][0]   - mn0), p1 = __expf(s[2*j][1]   - mn0);
            const float p2 = __expf(s[2*j][2]   - mn1), p3 = __expf(s[2*j][3]   - mn1);
            const float p4 = __expf(s[2*j+1][0] - mn0), p5 = __expf(s[2*j+1][1] - mn0);
            const float p6 = __expf(s[2*j+1][2] - mn1), p7 = __expf(s[2*j+1][3] - mn1);
            rs0 += (p0 + p1) + (p4 + p5);
            rs1 += (p2 + p3) + (p6 + p7);

            uint32_t ah_[4], al_[4];
            ah_[0] = pack_bf16(p0, p1); ah_[1] = pack_bf16(p2, p3);
            ah_[2] = pack_bf16(p4, p5); ah_[3] = pack_bf16(p6, p7);
            al_[0] = pack_lo(p0, p1, ah_[0]); al_[1] = pack_lo(p2, p3, ah_[1]);
            al_[2] = pack_lo(p4, p5, ah_[2]); al_[3] = pack_lo(p6, p7, ah_[3]);

            #pragma unroll
            for (int q = 0; q < 4; q++) {
                uint32_t tvh[4], tvl[4];
                const uint32_t off = (uint32_t)(16 * j + vrow) * TS + q * 32 + vcolb;
                ldsm_x4_trans(tvh, sVH + off);
                ldsm_x4_trans(tvl, sVL + off);
                // alternate accumulators: same-acc distance 2
                mma_bf16(o[2*q],   ah_, tvh[0], tvh[1]);
                mma_bf16(o[2*q+1], ah_, tvh[2], tvh[3]);
                mma_bf16(o[2*q],   al_, tvh[0], tvh[1]);
                mma_bf16(o[2*q+1], al_, tvh[2], tvh[3]);
                mma_bf16(o[2*q],   ah_, tvl[0], tvl[1]);
                mma_bf16(o[2*q+1], ah_, tvl[2], tvl[3]);
            }
        }
        #pragma unroll
        for (int d = 1; d < 4; d <<= 1) {
            rs0 += __shfl_xor_sync(0xffffffffu, rs0, d);
            rs1 += __shfl_xor_sync(0xffffffffu, rs1, d);
        }
        l0 = l0 * c0 + rs0;
        l1 = l1 * c1 + rs1;

        __syncthreads();
    }

    const float i0 = 1.0f / l0, i1 = 1.0f / l1;
    const int row0 = b * Sc + qBase + wid * 16 + g;
    #pragma unroll
    for (int nt = 0; nt < 8; nt++) {
        const int col = h * HDc + nt * 8 + tg * 2;
        const float v0 = o[nt][0] * i0, v1 = o[nt][1] * i0;
        const float v2 = o[nt][2] * i1, v3 = o[nt][3] * i1;
        const uint32_t h0 = pack_bf16(v0, v1), h1 = pack_bf16(v2, v3);
        *(uint32_t*)(g_xh + (size_t)row0 * Dc + col)       = h0;
        *(uint32_t*)(g_xl + (size_t)row0 * Dc + col)       = pack_lo(v0, v1, h0);
        *(uint32_t*)(g_xh + (size_t)(row0 + 8) * Dc + col) = h1;
        *(uint32_t*)(g_xl + (size_t)(row0 + 8) * Dc + col) = pack_lo(v2, v3, h1);
    }
}

// ---------------------------------------------------------------------------
// Launch: 5 kernels
// ---------------------------------------------------------------------------
extern "C" void kernel_launch(void* const* d_in, const int* in_sizes, int n_in,
                              void* d_out, int out_size)
{
    (void)in_sizes; (void)n_in; (void)out_size;

    const float* hs   = (const float*)d_in[0];
    const float* mask = (const float*)d_in[1];
    const float* Wq   = (const float*)d_in[2];
    const float* bq   = (const float*)d_in[3];
    const float* Wk   = (const float*)d_in[4];
    const float* bk   = (const float*)d_in[5];
    const float* Wv   = (const float*)d_in[6];
    const float* bv   = (const float*)d_in[7];
    const float* Wo   = (const float*)d_in[8];
    const float* bo   = (const float*)d_in[9];
    float* out = (float*)d_out;

    static bool attrDone = false;
    if (!attrDone) {
        cudaFuncSetAttribute(flash_kernel,
                             cudaFuncAttributeMaxDynamicSharedMemorySize, FLASH_SMEM);
        attrDone = true;
    }

    const int nX4 = Mc * Dc / 4;   // 1,048,576
    const int nW4 = Dc * Dc / 4;   // 262,144
    const dim3 gGemm(Dc / 128, Mc / 128);        // (8, 32)
    const dim3 gQKV(Dc / 128, Mc / 128, 3);      // (8, 32, 3)
    const dim3 gFlash(Sc / 128, Bc * Hc);        // (16, 32)
    const dim3 gW4((nW4 + 255) / 256, 4);

    split_x<<<(nX4 + 255) / 256, 256>>>(hs, nX4);
    split_w4<<<gW4, 256>>>(Wq, Wk, Wv, Wo, nW4);

    proj_qkv<<<gQKV, 256, SMEM_BYTES>>>(bq, bk, bv);

    flash_kernel<<<gFlash, 256, FLASH_SMEM>>>(mask);

    proj_o<<<gGemm, 256, SMEM_BYTES>>>(bo, out);
}

// round 15
// speedup vs baseline: 1.1319x; 1.0821x over previous
#include <cuda_runtime.h>
#include <cuda_bf16.h>
#include <cuda_fp16.h>
#include <cstdint>
#include <cstddef>

// Problem constants: B=2, S=2048, D=1024, H=16, HD=64
constexpr int Bc  = 2;
constexpr int Sc  = 2048;
constexpr int Dc  = 1024;
constexpr int Hc  = 16;
constexpr int HDc = 64;
constexpr int Mc  = Bc * Sc;   // 4096

// ---------------------------------------------------------------------------
// Static device scratch
//  - X / W buffers: bf16 hi/lo (3-term projections, proven 1.5e-5 accuracy)
//  - Q: fp16 hi only; K/V: fp16 hi/lo (flash 2-term scheme)
// ---------------------------------------------------------------------------
__device__ __nv_bfloat16 g_xh[(size_t)Mc * Dc];   // activations hi (reused for attn-out)
__device__ __nv_bfloat16 g_xl[(size_t)Mc * Dc];   // activations lo

__device__ __nv_bfloat16 g_wqh[(size_t)Dc * Dc];
__device__ __nv_bfloat16 g_wql[(size_t)Dc * Dc];
__device__ __nv_bfloat16 g_wkh[(size_t)Dc * Dc];
__device__ __nv_bfloat16 g_wkl[(size_t)Dc * Dc];
__device__ __nv_bfloat16 g_wvh[(size_t)Dc * Dc];
__device__ __nv_bfloat16 g_wvl[(size_t)Dc * Dc];
__device__ __nv_bfloat16 g_woh[(size_t)Dc * Dc];
__device__ __nv_bfloat16 g_wol[(size_t)Dc * Dc];

__device__ __half g_qh[(size_t)Bc * Hc * Sc * HDc];   // Q hi (fp16; no lo needed)
__device__ __half g_kh[(size_t)Bc * Hc * Sc * HDc];   // K hi
__device__ __half g_kl[(size_t)Bc * Hc * Sc * HDc];   // K lo
__device__ __half g_vh[(size_t)Bc * Hc * Sc * HDc];   // V hi
__device__ __half g_vl[(size_t)Bc * Hc * Sc * HDc];   // V lo

// ---------------------------------------------------------------------------
// PTX helpers (baseline ISA only — compute_103 safe)
// ---------------------------------------------------------------------------
__device__ __forceinline__ uint32_t smem_to_u32(const void* p) {
    uint32_t a;
    asm("{ .reg .u64 t; cvta.to.shared.u64 t, %1; cvt.u32.u64 %0, t; }"
        : "=r"(a) : "l"(p));
    return a;
}
__device__ __forceinline__ void cp_async16(uint32_t dst, const void* src) {
    asm volatile("cp.async.cg.shared.global [%0], [%1], 16;"
                 :: "r"(dst), "l"(src) : "memory");
}
__device__ __forceinline__ void cp_commit() {
    asm volatile("cp.async.commit_group;" ::: "memory");
}
__device__ __forceinline__ void cp_wait0() {
    asm volatile("cp.async.wait_group 0;" ::: "memory");
}
__device__ __forceinline__ void cp_wait1() {
    asm volatile("cp.async.wait_group 1;" ::: "memory");
}
__device__ __forceinline__ void ldsm_x4(uint32_t (&r)[4], uint32_t addr) {
    asm volatile("ldmatrix.sync.aligned.m8n8.x4.shared.b16 {%0,%1,%2,%3}, [%4];"
                 : "=r"(r[0]), "=r"(r[1]), "=r"(r[2]), "=r"(r[3]) : "r"(addr));
}
__device__ __forceinline__ void ldsm_x4_trans(uint32_t (&r)[4], uint32_t addr) {
    asm volatile("ldmatrix.sync.aligned.m8n8.x4.trans.shared.b16 {%0,%1,%2,%3}, [%4];"
                 : "=r"(r[0]), "=r"(r[1]), "=r"(r[2]), "=r"(r[3]) : "r"(addr));
}
__device__ __forceinline__ void mma_bf16(float (&d)[4], const uint32_t (&a)[4],
                                         const uint32_t b0, const uint32_t b1) {
    asm volatile(
        "mma.sync.aligned.m16n8k16.row.col.f32.bf16.bf16.f32 "
        "{%0,%1,%2,%3}, {%4,%5,%6,%7}, {%8,%9}, {%0,%1,%2,%3};"
        : "+f"(d[0]), "+f"(d[1]), "+f"(d[2]), "+f"(d[3])
        : "r"(a[0]), "r"(a[1]), "r"(a[2]), "r"(a[3]), "r"(b0), "r"(b1));
}
__device__ __forceinline__ void mma_f16(float (&d)[4], const uint32_t (&a)[4],
                                        const uint32_t b0, const uint32_t b1) {
    asm volatile(
        "mma.sync.aligned.m16n8k16.row.col.f32.f16.f16.f32 "
        "{%0,%1,%2,%3}, {%4,%5,%6,%7}, {%8,%9}, {%0,%1,%2,%3};"
        : "+f"(d[0]), "+f"(d[1]), "+f"(d[2]), "+f"(d[3])
        : "r"(a[0]), "r"(a[1]), "r"(a[2]), "r"(a[3]), "r"(b0), "r"(b1));
}
__device__ __forceinline__ uint32_t pack_bf16(float x, float y) {
    __nv_bfloat162 t = __floats2bfloat162_rn(x, y);
    return *reinterpret_cast<uint32_t*>(&t);
}
__device__ __forceinline__ uint32_t pack_lo(float x, float y, uint32_t hp) {
    __nv_bfloat162 hh = *reinterpret_cast<__nv_bfloat162*>(&hp);
    float2 hf = __bfloat1622float2(hh);
    __nv_bfloat162 t = __floats2bfloat162_rn(x - hf.x, y - hf.y);
    return *reinterpret_cast<uint32_t*>(&t);
}
__device__ __forceinline__ uint32_t pack_h16(float x, float y) {
    __half2 t = __floats2half2_rn(x, y);
    return *reinterpret_cast<uint32_t*>(&t);
}
__device__ __forceinline__ uint32_t pack_h16lo(float x, float y, uint32_t hp) {
    __half2 hh = *reinterpret_cast<__half2*>(&hp);
    float2 hf = __half22float2(hh);
    __half2 t = __floats2half2_rn(x - hf.x, y - hf.y);
    return *reinterpret_cast<uint32_t*>(&t);
}

// ---------------------------------------------------------------------------
// Splits (unchanged)
// ---------------------------------------------------------------------------
__global__ void split_x(const float* __restrict__ src, int n4)
{
    const int i = blockIdx.x * blockDim.x + threadIdx.x;
    if (i >= n4) return;
    float4 v = ((const float4*)src)[i];
    __nv_bfloat162 h01 = __floats2bfloat162_rn(v.x, v.y);
    __nv_bfloat162 h23 = __floats2bfloat162_rn(v.z, v.w);
    float2 f01 = __bfloat1622float2(h01);
    float2 f23 = __bfloat1622float2(h23);
    __nv_bfloat162 l01 = __floats2bfloat162_rn(v.x - f01.x, v.y - f01.y);
    __nv_bfloat162 l23 = __floats2bfloat162_rn(v.z - f23.x, v.w - f23.y);
    uint2 H, L;
    H.x = *reinterpret_cast<uint32_t*>(&h01); H.y = *reinterpret_cast<uint32_t*>(&h23);
    L.x = *reinterpret_cast<uint32_t*>(&l01); L.y = *reinterpret_cast<uint32_t*>(&l23);
    ((uint2*)g_xh)[i] = H;
    ((uint2*)g_xl)[i] = L;
}

__global__ void split_w4(const float* __restrict__ Wq, const float* __restrict__ Wk,
                         const float* __restrict__ Wv, const float* __restrict__ Wo,
                         int n4)
{
    const int i = blockIdx.x * blockDim.x + threadIdx.x;
    if (i >= n4) return;
    const int w = blockIdx.y;
    const float* src = (w == 0) ? Wq : (w == 1) ? Wk : (w == 2) ? Wv : Wo;
    __nv_bfloat16* hi = (w == 0) ? g_wqh : (w == 1) ? g_wkh : (w == 2) ? g_wvh : g_woh;
    __nv_bfloat16* lo = (w == 0) ? g_wql : (w == 1) ? g_wkl : (w == 2) ? g_wvl : g_wol;

    float4 v = ((const float4*)src)[i];
    __nv_bfloat162 h01 = __floats2bfloat162_rn(v.x, v.y);
    __nv_bfloat162 h23 = __floats2bfloat162_rn(v.z, v.w);
    float2 f01 = __bfloat1622float2(h01);
    float2 f23 = __bfloat1622float2(h23);
    __nv_bfloat162 l01 = __floats2bfloat162_rn(v.x - f01.x, v.y - f01.y);
    __nv_bfloat162 l23 = __floats2bfloat162_rn(v.z - f23.x, v.w - f23.y);
    uint2 H, L;
    H.x = *reinterpret_cast<uint32_t*>(&h01); H.y = *reinterpret_cast<uint32_t*>(&h23);
    L.x = *reinterpret_cast<uint32_t*>(&l01); L.y = *reinterpret_cast<uint32_t*>(&l23);
    ((uint2*)hi)[i] = H;
    ((uint2*)lo)[i] = L;
}

// ---------------------------------------------------------------------------
// HMMA mainloop (R14, term-major): acc += (Ah+Al)*(Bh+Bl)^T, bf16 3-term.
// Single buffer; 2 CTAs/SM hide latency.
// ---------------------------------------------------------------------------
constexpr int SMEM_BYTES = 4 * 128 * 80;   // 40960

__device__ __forceinline__ void gemm_mainloop(
    float (&acc)[4][4][4],
    const __nv_bfloat16* __restrict__ Ah, const __nv_bfloat16* __restrict__ Al,
    const __nv_bfloat16* __restrict__ Bh, const __nv_bfloat16* __restrict__ Bl,
    int ldA, int ldB, int K, char* smem)
{
    const int tid  = threadIdx.x;
    const int wid  = tid >> 5, lane = tid & 31;
    const int wm   = wid >> 2, wn = wid & 3;
    const uint32_t sb  = smem_to_u32(smem);
    const uint32_t sAh = sb, sAl = sb + 10240, sBh = sb + 20480, sBl = sb + 30720;

    const int lr = tid >> 2;
    const int lc = (tid & 3) * 8;

    const int arow = wm * 64 + (lane & 15);
    const int acol = (lane >> 4) << 3;
    const uint32_t aoff = (uint32_t)arow * 80 + acol * 2;
    const int brow = wn * 32 + (lane & 7) + ((lane & 16) >> 1);
    const int bcol = lane & 8;
    const uint32_t boff = (uint32_t)brow * 80 + bcol * 2;

    const int nchunks = K >> 5;
    for (int ch = 0; ch < nchunks; ch++) {
        const int k0 = ch * 32;
        #pragma unroll
        for (int it = 0; it < 2; it++) {
            const int r = lr + it * 64;
            const uint32_t so = (uint32_t)r * 80 + lc * 2;
            cp_async16(sAh + so, Ah + (size_t)r * ldA + k0 + lc);
            cp_async16(sAl + so, Al + (size_t)r * ldA + k0 + lc);
            cp_async16(sBh + so, Bh + (size_t)r * ldB + k0 + lc);
            cp_async16(sBl + so, Bl + (size_t)r * ldB + k0 + lc);
        }
        cp_commit();
        cp_wait0();
        __syncthreads();

        #pragma unroll
        for (int ks = 0; ks < 2; ks++) {
            uint32_t ah[4][4], al[4][4];
            uint32_t bh0[4], bh1[4], bl0[4], bl1[4];
            #pragma unroll
            for (int mt = 0; mt < 4; mt++) {
                const uint32_t off = aoff + (uint32_t)mt * 16 * 80 + ks * 32;
                ldsm_x4(ah[mt], sAh + off);
                ldsm_x4(al[mt], sAl + off);
            }
            #pragma unroll
            for (int p = 0; p < 2; p++) {
                const uint32_t off = boff + (uint32_t)p * 16 * 80 + ks * 32;
                uint32_t t[4];
                ldsm_x4(t, sBh + off);
                bh0[2*p] = t[0]; bh1[2*p] = t[1]; bh0[2*p+1] = t[2]; bh1[2*p+1] = t[3];
                ldsm_x4(t, sBl + off);
                bl0[2*p] = t[0]; bl1[2*p] = t[1]; bl0[2*p+1] = t[2]; bl1[2*p+1] = t[3];
            }
            #pragma unroll
            for (int mt = 0; mt < 4; mt++)
                #pragma unroll
                for (int nt = 0; nt < 4; nt++)
                    mma_bf16(acc[mt][nt], ah[mt], bh0[nt], bh1[nt]);
            #pragma unroll
            for (int mt = 0; mt < 4; mt++)
                #pragma unroll
                for (int nt = 0; nt < 4; nt++)
                    mma_bf16(acc[mt][nt], ah[mt], bl0[nt], bl1[nt]);
            #pragma unroll
            for (int mt = 0; mt < 4; mt++)
                #pragma unroll
                for (int nt = 0; nt < 4; nt++)
                    mma_bf16(acc[mt][nt], al[mt], bh0[nt], bh1[nt]);
        }
        __syncthreads();
    }
}

// ---------------------------------------------------------------------------
// Merged Q/K/V projection: Q -> fp16 hi only; K/V -> fp16 hi+lo.
// ---------------------------------------------------------------------------
__global__ __launch_bounds__(256)
void proj_qkv(const float* __restrict__ bq, const float* __restrict__ bk,
              const float* __restrict__ bv)
{
    extern __shared__ __align__(16) char smem[];
    const int which = blockIdx.z;
    const int mBase = blockIdx.y * 128;
    const int nBase = blockIdx.x * 128;

    const __nv_bfloat16* wh = (which == 0) ? g_wqh : (which == 1) ? g_wkh : g_wvh;
    const __nv_bfloat16* wl = (which == 0) ? g_wql : (which == 1) ? g_wkl : g_wvl;
    const float* bias       = (which == 0) ? bq    : (which == 1) ? bk    : bv;
    __half* dh              = (which == 0) ? g_qh  : (which == 1) ? g_kh  : g_vh;
    __half* dl              = (which == 0) ? nullptr : (which == 1) ? g_kl : g_vl;

    float acc[4][4][4];
    #pragma unroll
    for (int i = 0; i < 4; i++)
        #pragma unroll
        for (int j = 0; j < 4; j++)
            #pragma unroll
            for (int e = 0; e < 4; e++) acc[i][j][e] = 0.0f;

    gemm_mainloop(acc,
                  g_xh + (size_t)mBase * Dc, g_xl + (size_t)mBase * Dc,
                  wh + (size_t)nBase * Dc, wl + (size_t)nBase * Dc,
                  Dc, Dc, Dc, smem);

    const int tid  = threadIdx.x;
    const int wid  = tid >> 5, lane = tid & 31;
    const int wm   = wid >> 2, wn = wid & 3;
    const int g    = lane >> 2, tg = lane & 3;

    #pragma unroll
    for (int mt = 0; mt < 4; mt++) {
        const int r0 = mBase + wm * 64 + mt * 16 + g;
        #pragma unroll
        for (int nt = 0; nt < 4; nt++) {
            const int c0 = nBase + wn * 32 + nt * 8 + tg * 2;
            const float b0 = bias[c0], b1 = bias[c0 + 1];
            #pragma unroll
            for (int half = 0; half < 2; half++) {
                const int r = r0 + half * 8;
                const float v0 = acc[mt][nt][half * 2 + 0] + b0;
                const float v1 = acc[mt][nt][half * 2 + 1] + b1;
                const int b  = r >> 11, s = r & (Sc - 1);
                const int h  = c0 >> 6, hd = c0 & (HDc - 1);
                const size_t idx = (((size_t)(b * Hc + h)) * Sc + s) * HDc + hd;
                const uint32_t hp = pack_h16(v0, v1);
                *(uint32_t*)(dh + idx) = hp;
                if (which != 0)
                    *(uint32_t*)(dl + idx) = pack_h16lo(v0, v1, hp);
            }
        }
    }
}

// ---------------------------------------------------------------------------
// Final O projection: out = AO * Wo^T + bo  (fp32 out; bf16 3-term)
// ---------------------------------------------------------------------------
__global__ __launch_bounds__(256)
void proj_o(const float* __restrict__ bias, float* __restrict__ outPlain)
{
    extern __shared__ __align__(16) char smem[];
    const int mBase = blockIdx.y * 128;
    const int nBase = blockIdx.x * 128;

    float acc[4][4][4];
    #pragma unroll
    for (int i = 0; i < 4; i++)
        #pragma unroll
        for (int j = 0; j < 4; j++)
            #pragma unroll
            for (int e = 0; e < 4; e++) acc[i][j][e] = 0.0f;

    gemm_mainloop(acc,
                  g_xh + (size_t)mBase * Dc, g_xl + (size_t)mBase * Dc,
                  g_woh + (size_t)nBase * Dc, g_wol + (size_t)nBase * Dc,
                  Dc, Dc, Dc, smem);

    const int tid  = threadIdx.x;
    const int wid  = tid >> 5, lane = tid & 31;
    const int wm   = wid >> 2, wn = wid & 3;
    const int g    = lane >> 2, tg = lane & 3;

    #pragma unroll
    for (int mt = 0; mt < 4; mt++) {
        const int r0 = mBase + wm * 64 + mt * 16 + g;
        #pragma unroll
        for (int nt = 0; nt < 4; nt++) {
            const int c0 = nBase + wn * 32 + nt * 8 + tg * 2;
            const float b0 = bias[c0], b1 = bias[c0 + 1];
            #pragma unroll
            for (int half = 0; half < 2; half++) {
                const int r = r0 + half * 8;
                const float v0 = acc[mt][nt][half * 2 + 0] + b0;
                const float v1 = acc[mt][nt][half * 2 + 1] + b1;
                *(float2*)(outPlain + (size_t)r * Dc + c0) = make_float2(v0, v1);
            }
        }
    }
}

// ---------------------------------------------------------------------------
// Fused flash attention, fp16 2-term:
//   S = Qh·(Kh + Kl)   (Q rounded to fp16; K exact via hi/lo)
//   O = Ph·(Vh + Vl)   (P rounded to fp16; V exact via hi/lo)
// MMAs per warp-iter: 128 (was 192). Q-lo tile gone: smem 92160 B.
// Mask rows prefetched into L1 before the QK MMA phase.
// ---------------------------------------------------------------------------
constexpr int TS        = 144;
constexpr int QTILE_B   = 128 * TS;                 // 18432 (hi only)
constexpr int KVTILE_B  = 64 * TS;                  // 9216
constexpr int KVSTAGE_B = 4 * KVTILE_B;             // 36864
constexpr int FLASH_SMEM = QTILE_B + 2 * KVSTAGE_B; // 92160

__global__ __launch_bounds__(256, 2)
void flash_kernel(const float* __restrict__ mask)
{
    extern __shared__ __align__(16) char smem[];
    const uint32_t sb = smem_to_u32(smem);
    const int tid = threadIdx.x, wid = tid >> 5, lane = tid & 31;
    const int g = lane >> 2, tg = lane & 3;
    const int qBase = blockIdx.x * 128;
    const int bh = blockIdx.y;
    const int b = bh >> 4, h = bh & (Hc - 1);

    const size_t bhOff = (size_t)bh * Sc * HDc;
    const __half* __restrict__ Qh = g_qh + bhOff + (size_t)qBase * HDc;
    const __half* __restrict__ Kh = g_kh + bhOff;
    const __half* __restrict__ Kl = g_kl + bhOff;
    const __half* __restrict__ Vh = g_vh + bhOff;
    const __half* __restrict__ Vl = g_vl + bhOff;

    const uint32_t sQH = sb;

    // ---- Q hi tile load (128 rows x 128B) ----
    #pragma unroll
    for (int i = 0; i < 4; i++) {
        const int c = tid + i * 256;
        const int r = c >> 3, cc = c & 7;
        const uint32_t so = (uint32_t)r * TS + cc * 16;
        cp_async16(sQH + so, Qh + (size_t)r * HDc + cc * 8);
    }
    cp_commit();

    // ---- K/V 64-key tile loader ----
    auto loadKV = [&](int kb, int st) {
        const uint32_t bufB = sb + QTILE_B + (uint32_t)st * KVSTAGE_B;
        const size_t base = (size_t)kb * 64 * HDc;
        #pragma unroll
        for (int i = 0; i < 2; i++) {
            const int c = tid + i * 256;
            const int r = c >> 3, cc = c & 7;
            const uint32_t so = (uint32_t)r * TS + cc * 16;
            const size_t go = base + (size_t)r * HDc + cc * 8;
            cp_async16(bufB                + so, Kh + go);
            cp_async16(bufB +     KVTILE_B + so, Kl + go);
            cp_async16(bufB + 2 * KVTILE_B + so, Vh + go);
            cp_async16(bufB + 3 * KVTILE_B + so, Vl + go);
        }
        cp_commit();
    };
    loadKV(0, 0);
    cp_wait0();
    __syncthreads();

    // ---- Q fragments (hi only), register-resident ----
    uint32_t qah[4][4];
    {
        const uint32_t arow = (uint32_t)(wid * 16 + (lane & 15));
        const uint32_t acolb = (uint32_t)((lane >> 4) * 16);
        #pragma unroll
        for (int kk = 0; kk < 4; kk++)
            ldsm_x4(qah[kk], sQH + arow * TS + kk * 32 + acolb);
    }

    float o[8][4];
    #pragma unroll
    for (int i = 0; i < 8; i++)
        #pragma unroll
        for (int e = 0; e < 4; e++) o[i][e] = 0.0f;
    float mrun0 = -3e38f, mrun1 = -3e38f, l0 = 0.0f, l1 = 0.0f;

    const float* __restrict__ M0 =
        mask + ((size_t)b * Sc + qBase + wid * 16 + g) * Sc;

    const uint32_t brow = (uint32_t)((lane & 7) + ((lane & 16) >> 1));
    const uint32_t bcolb = (uint32_t)((lane & 8) << 1);
    const uint32_t vrow = (uint32_t)((lane & 7) + (lane & 8));
    const uint32_t vcolb = (uint32_t)(lane & 16);

    for (int kb = 0; kb < 32; kb++) {
        if (kb + 1 < 32) { loadKV(kb + 1, (kb + 1) & 1); cp_wait1(); }
        else             { cp_wait0(); }
        __syncthreads();

        // prefetch this iteration's mask rows ~3000 cyc before use
        const float* Mk0 = M0 + (size_t)kb * 64;
        if (tg == 0) {
            const float* pm8 = Mk0 + 8 * (size_t)Sc;
            asm volatile("prefetch.global.L1 [%0];" :: "l"(Mk0));
            asm volatile("prefetch.global.L1 [%0];" :: "l"(Mk0 + 32));
            asm volatile("prefetch.global.L1 [%0];" :: "l"(pm8));
            asm volatile("prefetch.global.L1 [%0];" :: "l"(pm8 + 32));
        }

        const uint32_t bufB = sb + QTILE_B + (uint32_t)(kb & 1) * KVSTAGE_B;
        const uint32_t sKH = bufB, sKL = bufB + KVTILE_B;
        const uint32_t sVH = bufB + 2 * KVTILE_B, sVL = bufB + 3 * KVTILE_B;

        // ---- S = Qh Kh^T + Qh Kl^T  (4 MMAs per (p,kk)) ----
        float s[8][4];
        #pragma unroll
        for (int nt = 0; nt < 8; nt++)
            #pragma unroll
            for (int e = 0; e < 4; e++) s[nt][e] = 0.0f;

        #pragma unroll
        for (int p = 0; p < 4; p++) {
            #pragma unroll
            for (int kk = 0; kk < 4; kk++) {
                uint32_t tbh[4], tbl[4];
                const uint32_t off = (uint32_t)(16 * p + brow) * TS + kk * 32 + bcolb;
                ldsm_x4(tbh, sKH + off);
                ldsm_x4(tbl, sKL + off);
                mma_f16(s[2*p],   qah[kk], tbh[0], tbh[1]);
                mma_f16(s[2*p+1], qah[kk], tbh[2], tbh[3]);
                mma_f16(s[2*p],   qah[kk], tbl[0], tbl[1]);
                mma_f16(s[2*p+1], qah[kk], tbl[2], tbl[3]);
            }
        }

        // ---- scale + mask + row max ----
        float mx0 = -3e38f, mx1 = -3e38f;
        #pragma unroll
        for (int nt = 0; nt < 8; nt++) {
            const int col = nt * 8 + tg * 2;
            const float2 a = *(const float2*)(Mk0 + col);
            const float2 c = *(const float2*)(Mk0 + 8 * (size_t)Sc + col);
            s[nt][0] = fmaf(s[nt][0], 0.125f, a.x);
            s[nt][1] = fmaf(s[nt][1], 0.125f, a.y);
            s[nt][2] = fmaf(s[nt][2], 0.125f, c.x);
            s[nt][3] = fmaf(s[nt][3], 0.125f, c.y);
            mx0 = fmaxf(mx0, fmaxf(s[nt][0], s[nt][1]));
            mx1 = fmaxf(mx1, fmaxf(s[nt][2], s[nt][3]));
        }
        #pragma unroll
        for (int d = 1; d < 4; d <<= 1) {
            mx0 = fmaxf(mx0, __shfl_xor_sync(0xffffffffu, mx0, d));
            mx1 = fmaxf(mx1, __shfl_xor_sync(0xffffffffu, mx1, d));
        }
        const float mn0 = fmaxf(mrun0, mx0), mn1 = fmaxf(mrun1, mx1);
        const float c0 = __expf(mrun0 - mn0), c1 = __expf(mrun1 - mn1);
        mrun0 = mn0; mrun1 = mn1;
        #pragma unroll
        for (int nt = 0; nt < 8; nt++) {
            o[nt][0] *= c0; o[nt][1] *= c0;
            o[nt][2] *= c1; o[nt][3] *= c1;
        }

        // ---- exp, pack P to fp16 (hi only), PV accumulate ----
        float rs0 = 0.0f, rs1 = 0.0f;
        #pragma unroll
        for (int j = 0; j < 4; j++) {
            const float p0 = __expf(s[2*j][0]   - mn0), p1 = __expf(s[2*j][1]   - mn0);
            const float p2 = __expf(s[2*j][2]   - mn1), p3 = __expf(s[2*j][3]   - mn1);
            const float p4 = __expf(s[2*j+1][0] - mn0), p5 = __expf(s[2*j+1][1] - mn0);
            const float p6 = __expf(s[2*j+1][2] - mn1), p7 = __expf(s[2*j+1][3] - mn1);
            rs0 += (p0 + p1) + (p4 + p5);
            rs1 += (p2 + p3) + (p6 + p7);

            uint32_t ah_[4];
            ah_[0] = pack_h16(p0, p1); ah_[1] = pack_h16(p2, p3);
            ah_[2] = pack_h16(p4, p5); ah_[3] = pack_h16(p6, p7);

            #pragma unroll
            for (int q = 0; q < 4; q++) {
                uint32_t tvh[4], tvl[4];
                const uint32_t off = (uint32_t)(16 * j + vrow) * TS + q * 32 + vcolb;
                ldsm_x4_trans(tvh, sVH + off);
                ldsm_x4_trans(tvl, sVL + off);
                mma_f16(o[2*q],   ah_, tvh[0], tvh[1]);
                mma_f16(o[2*q+1], ah_, tvh[2], tvh[3]);
                mma_f16(o[2*q],   ah_, tvl[0], tvl[1]);
                mma_f16(o[2*q+1], ah_, tvl[2], tvl[3]);
            }
        }
        #pragma unroll
        for (int d = 1; d < 4; d <<= 1) {
            rs0 += __shfl_xor_sync(0xffffffffu, rs0, d);
            rs1 += __shfl_xor_sync(0xffffffffu, rs1, d);
        }
        l0 = l0 * c0 + rs0;
        l1 = l1 * c1 + rs1;

        __syncthreads();
    }

    // ---- epilogue: O/l -> bf16 hi/lo into g_xh/g_xl [4096,1024] ----
    const float i0 = 1.0f / l0, i1 = 1.0f / l1;
    const int row0 = b * Sc + qBase + wid * 16 + g;
    #pragma unroll
    for (int nt = 0; nt < 8; nt++) {
        const int col = h * HDc + nt * 8 + tg * 2;
        const float v0 = o[nt][0] * i0, v1 = o[nt][1] * i0;
        const float v2 = o[nt][2] * i1, v3 = o[nt][3] * i1;
        const uint32_t h0 = pack_bf16(v0, v1), h1 = pack_bf16(v2, v3);
        *(uint32_t*)(g_xh + (size_t)row0 * Dc + col)       = h0;
        *(uint32_t*)(g_xl + (size_t)row0 * Dc + col)       = pack_lo(v0, v1, h0);
        *(uint32_t*)(g_xh + (size_t)(row0 + 8) * Dc + col) = h1;
        *(uint32_t*)(g_xl + (size_t)(row0 + 8) * Dc + col) = pack_lo(v2, v3, h1);
    }
}

// ---------------------------------------------------------------------------
// Launch: 5 kernels
// ---------------------------------------------------------------------------
extern "C" void kernel_launch(void* const* d_in, const int* in_sizes, int n_in,
                              void* d_out, int out_size)
{
    (void)in_sizes; (void)n_in; (void)out_size;

    const float* hs   = (const float*)d_in[0];
    const float* mask = (const float*)d_in[1];
    const float* Wq   = (const float*)d_in[2];
    const float* bq   = (const float*)d_in[3];
    const float* Wk   = (const float*)d_in[4];
    const float* bk   = (const float*)d_in[5];
    const float* Wv   = (const float*)d_in[6];
    const float* bv   = (const float*)d_in[7];
    const float* Wo   = (const float*)d_in[8];
    const float* bo   = (const float*)d_in[9];
    float* out = (float*)d_out;

    static bool attrDone = false;
    if (!attrDone) {
        cudaFuncSetAttribute(flash_kernel,
                             cudaFuncAttributeMaxDynamicSharedMemorySize, FLASH_SMEM);
        attrDone = true;
    }

    const int nX4 = Mc * Dc / 4;   // 1,048,576
    const int nW4 = Dc * Dc / 4;   // 262,144
    const dim3 gGemm(Dc / 128, Mc / 128);        // (8, 32)
    const dim3 gQKV(Dc / 128, Mc / 128, 3);      // (8, 32, 3)
    const dim3 gFlash(Sc / 128, Bc * Hc);        // (16, 32)
    const dim3 gW4((nW4 + 255) / 256, 4);

    split_x<<<(nX4 + 255) / 256, 256>>>(hs, nX4);
    split_w4<<<gW4, 256>>>(Wq, Wk, Wv, Wo, nW4);

    proj_qkv<<<gQKV, 256, SMEM_BYTES>>>(bq, bk, bv);

    flash_kernel<<<gFlash, 256, FLASH_SMEM>>>(mask);

    proj_o<<<gGemm, 256, SMEM_BYTES>>>(bo, out);
}

// round 16
// speedup vs baseline: 1.3336x; 1.1782x over previous
#include <cuda_runtime.h>
#include <cuda_bf16.h>
#include <cuda_fp16.h>
#include <cstdint>
#include <cstddef>

// Problem constants: B=2, S=2048, D=1024, H=16, HD=64
constexpr int Bc  = 2;
constexpr int Sc  = 2048;
constexpr int Dc  = 1024;
constexpr int Hc  = 16;
constexpr int HDc = 64;
constexpr int Mc  = Bc * Sc;   // 4096

// ---------------------------------------------------------------------------
// Static device scratch
//  - X / W buffers: bf16 hi/lo (3-term projections, 1.5e-5 accuracy)
//  - Q / K / V: fp16 hi ONLY (pure-fp16 flash; error budget ~4.6e-4)
// ---------------------------------------------------------------------------
__device__ __nv_bfloat16 g_xh[(size_t)Mc * Dc];   // activations hi (reused for attn-out)
__device__ __nv_bfloat16 g_xl[(size_t)Mc * Dc];   // activations lo

__device__ __nv_bfloat16 g_wqh[(size_t)Dc * Dc];
__device__ __nv_bfloat16 g_wql[(size_t)Dc * Dc];
__device__ __nv_bfloat16 g_wkh[(size_t)Dc * Dc];
__device__ __nv_bfloat16 g_wkl[(size_t)Dc * Dc];
__device__ __nv_bfloat16 g_wvh[(size_t)Dc * Dc];
__device__ __nv_bfloat16 g_wvl[(size_t)Dc * Dc];
__device__ __nv_bfloat16 g_woh[(size_t)Dc * Dc];
__device__ __nv_bfloat16 g_wol[(size_t)Dc * Dc];

__device__ __half g_qh[(size_t)Bc * Hc * Sc * HDc];   // Q (fp16)
__device__ __half g_kh[(size_t)Bc * Hc * Sc * HDc];   // K (fp16)
__device__ __half g_vh[(size_t)Bc * Hc * Sc * HDc];   // V (fp16)

// ---------------------------------------------------------------------------
// PTX helpers (baseline ISA only — compute_103 safe)
// ---------------------------------------------------------------------------
__device__ __forceinline__ uint32_t smem_to_u32(const void* p) {
    uint32_t a;
    asm("{ .reg .u64 t; cvta.to.shared.u64 t, %1; cvt.u32.u64 %0, t; }"
        : "=r"(a) : "l"(p));
    return a;
}
__device__ __forceinline__ void cp_async16(uint32_t dst, const void* src) {
    asm volatile("cp.async.cg.shared.global [%0], [%1], 16;"
                 :: "r"(dst), "l"(src) : "memory");
}
__device__ __forceinline__ void cp_commit() {
    asm volatile("cp.async.commit_group;" ::: "memory");
}
__device__ __forceinline__ void cp_wait0() {
    asm volatile("cp.async.wait_group 0;" ::: "memory");
}
__device__ __forceinline__ void cp_wait1() {
    asm volatile("cp.async.wait_group 1;" ::: "memory");
}
__device__ __forceinline__ void ldsm_x4(uint32_t (&r)[4], uint32_t addr) {
    asm volatile("ldmatrix.sync.aligned.m8n8.x4.shared.b16 {%0,%1,%2,%3}, [%4];"
                 : "=r"(r[0]), "=r"(r[1]), "=r"(r[2]), "=r"(r[3]) : "r"(addr));
}
__device__ __forceinline__ void ldsm_x4_trans(uint32_t (&r)[4], uint32_t addr) {
    asm volatile("ldmatrix.sync.aligned.m8n8.x4.trans.shared.b16 {%0,%1,%2,%3}, [%4];"
                 : "=r"(r[0]), "=r"(r[1]), "=r"(r[2]), "=r"(r[3]) : "r"(addr));
}
__device__ __forceinline__ void mma_bf16(float (&d)[4], const uint32_t (&a)[4],
                                         const uint32_t b0, const uint32_t b1) {
    asm volatile(
        "mma.sync.aligned.m16n8k16.row.col.f32.bf16.bf16.f32 "
        "{%0,%1,%2,%3}, {%4,%5,%6,%7}, {%8,%9}, {%0,%1,%2,%3};"
        : "+f"(d[0]), "+f"(d[1]), "+f"(d[2]), "+f"(d[3])
        : "r"(a[0]), "r"(a[1]), "r"(a[2]), "r"(a[3]), "r"(b0), "r"(b1));
}
__device__ __forceinline__ void mma_f16(float (&d)[4], const uint32_t (&a)[4],
                                        const uint32_t b0, const uint32_t b1) {
    asm volatile(
        "mma.sync.aligned.m16n8k16.row.col.f32.f16.f16.f32 "
        "{%0,%1,%2,%3}, {%4,%5,%6,%7}, {%8,%9}, {%0,%1,%2,%3};"
        : "+f"(d[0]), "+f"(d[1]), "+f"(d[2]), "+f"(d[3])
        : "r"(a[0]), "r"(a[1]), "r"(a[2]), "r"(a[3]), "r"(b0), "r"(b1));
}
__device__ __forceinline__ uint32_t pack_bf16(float x, float y) {
    __nv_bfloat162 t = __floats2bfloat162_rn(x, y);
    return *reinterpret_cast<uint32_t*>(&t);
}
__device__ __forceinline__ uint32_t pack_lo(float x, float y, uint32_t hp) {
    __nv_bfloat162 hh = *reinterpret_cast<__nv_bfloat162*>(&hp);
    float2 hf = __bfloat1622float2(hh);
    __nv_bfloat162 t = __floats2bfloat162_rn(x - hf.x, y - hf.y);
    return *reinterpret_cast<uint32_t*>(&t);
}
__device__ __forceinline__ uint32_t pack_h16(float x, float y) {
    __half2 t = __floats2half2_rn(x, y);
    return *reinterpret_cast<uint32_t*>(&t);
}

// ---------------------------------------------------------------------------
// Splits (unchanged)
// ---------------------------------------------------------------------------
__global__ void split_x(const float* __restrict__ src, int n4)
{
    const int i = blockIdx.x * blockDim.x + threadIdx.x;
    if (i >= n4) return;
    float4 v = ((const float4*)src)[i];
    __nv_bfloat162 h01 = __floats2bfloat162_rn(v.x, v.y);
    __nv_bfloat162 h23 = __floats2bfloat162_rn(v.z, v.w);
    float2 f01 = __bfloat1622float2(h01);
    float2 f23 = __bfloat1622float2(h23);
    __nv_bfloat162 l01 = __floats2bfloat162_rn(v.x - f01.x, v.y - f01.y);
    __nv_bfloat162 l23 = __floats2bfloat162_rn(v.z - f23.x, v.w - f23.y);
    uint2 H, L;
    H.x = *reinterpret_cast<uint32_t*>(&h01); H.y = *reinterpret_cast<uint32_t*>(&h23);
    L.x = *reinterpret_cast<uint32_t*>(&l01); L.y = *reinterpret_cast<uint32_t*>(&l23);
    ((uint2*)g_xh)[i] = H;
    ((uint2*)g_xl)[i] = L;
}

__global__ void split_w4(const float* __restrict__ Wq, const float* __restrict__ Wk,
                         const float* __restrict__ Wv, const float* __restrict__ Wo,
                         int n4)
{
    const int i = blockIdx.x * blockDim.x + threadIdx.x;
    if (i >= n4) return;
    const int w = blockIdx.y;
    const float* src = (w == 0) ? Wq : (w == 1) ? Wk : (w == 2) ? Wv : Wo;
    __nv_bfloat16* hi = (w == 0) ? g_wqh : (w == 1) ? g_wkh : (w == 2) ? g_wvh : g_woh;
    __nv_bfloat16* lo = (w == 0) ? g_wql : (w == 1) ? g_wkl : (w == 2) ? g_wvl : g_wol;

    float4 v = ((const float4*)src)[i];
    __nv_bfloat162 h01 = __floats2bfloat162_rn(v.x, v.y);
    __nv_bfloat162 h23 = __floats2bfloat162_rn(v.z, v.w);
    float2 f01 = __bfloat1622float2(h01);
    float2 f23 = __bfloat1622float2(h23);
    __nv_bfloat162 l01 = __floats2bfloat162_rn(v.x - f01.x, v.y - f01.y);
    __nv_bfloat162 l23 = __floats2bfloat162_rn(v.z - f23.x, v.w - f23.y);
    uint2 H, L;
    H.x = *reinterpret_cast<uint32_t*>(&h01); H.y = *reinterpret_cast<uint32_t*>(&h23);
    L.x = *reinterpret_cast<uint32_t*>(&l01); L.y = *reinterpret_cast<uint32_t*>(&l23);
    ((uint2*)hi)[i] = H;
    ((uint2*)lo)[i] = L;
}

// ---------------------------------------------------------------------------
// HMMA mainloop (R14, term-major): acc += (Ah+Al)*(Bh+Bl)^T, bf16 3-term.
// Single buffer; 2 CTAs/SM hide latency.
// ---------------------------------------------------------------------------
constexpr int SMEM_BYTES = 4 * 128 * 80;   // 40960

__device__ __forceinline__ void gemm_mainloop(
    float (&acc)[4][4][4],
    const __nv_bfloat16* __restrict__ Ah, const __nv_bfloat16* __restrict__ Al,
    const __nv_bfloat16* __restrict__ Bh, const __nv_bfloat16* __restrict__ Bl,
    int ldA, int ldB, int K, char* smem)
{
    const int tid  = threadIdx.x;
    const int wid  = tid >> 5, lane = tid & 31;
    const int wm   = wid >> 2, wn = wid & 3;
    const uint32_t sb  = smem_to_u32(smem);
    const uint32_t sAh = sb, sAl = sb + 10240, sBh = sb + 20480, sBl = sb + 30720;

    const int lr = tid >> 2;
    const int lc = (tid & 3) * 8;

    const int arow = wm * 64 + (lane & 15);
    const int acol = (lane >> 4) << 3;
    const uint32_t aoff = (uint32_t)arow * 80 + acol * 2;
    const int brow = wn * 32 + (lane & 7) + ((lane & 16) >> 1);
    const int bcol = lane & 8;
    const uint32_t boff = (uint32_t)brow * 80 + bcol * 2;

    const int nchunks = K >> 5;
    for (int ch = 0; ch < nchunks; ch++) {
        const int k0 = ch * 32;
        #pragma unroll
        for (int it = 0; it < 2; it++) {
            const int r = lr + it * 64;
            const uint32_t so = (uint32_t)r * 80 + lc * 2;
            cp_async16(sAh + so, Ah + (size_t)r * ldA + k0 + lc);
            cp_async16(sAl + so, Al + (size_t)r * ldA + k0 + lc);
            cp_async16(sBh + so, Bh + (size_t)r * ldB + k0 + lc);
            cp_async16(sBl + so, Bl + (size_t)r * ldB + k0 + lc);
        }
        cp_commit();
        cp_wait0();
        __syncthreads();

        #pragma unroll
        for (int ks = 0; ks < 2; ks++) {
            uint32_t ah[4][4], al[4][4];
            uint32_t bh0[4], bh1[4], bl0[4], bl1[4];
            #pragma unroll
            for (int mt = 0; mt < 4; mt++) {
                const uint32_t off = aoff + (uint32_t)mt * 16 * 80 + ks * 32;
                ldsm_x4(ah[mt], sAh + off);
                ldsm_x4(al[mt], sAl + off);
            }
            #pragma unroll
            for (int p = 0; p < 2; p++) {
                const uint32_t off = boff + (uint32_t)p * 16 * 80 + ks * 32;
                uint32_t t[4];
                ldsm_x4(t, sBh + off);
                bh0[2*p] = t[0]; bh1[2*p] = t[1]; bh0[2*p+1] = t[2]; bh1[2*p+1] = t[3];
                ldsm_x4(t, sBl + off);
                bl0[2*p] = t[0]; bl1[2*p] = t[1]; bl0[2*p+1] = t[2]; bl1[2*p+1] = t[3];
            }
            #pragma unroll
            for (int mt = 0; mt < 4; mt++)
                #pragma unroll
                for (int nt = 0; nt < 4; nt++)
                    mma_bf16(acc[mt][nt], ah[mt], bh0[nt], bh1[nt]);
            #pragma unroll
            for (int mt = 0; mt < 4; mt++)
                #pragma unroll
                for (int nt = 0; nt < 4; nt++)
                    mma_bf16(acc[mt][nt], ah[mt], bl0[nt], bl1[nt]);
            #pragma unroll
            for (int mt = 0; mt < 4; mt++)
                #pragma unroll
                for (int nt = 0; nt < 4; nt++)
                    mma_bf16(acc[mt][nt], al[mt], bh0[nt], bh1[nt]);
        }
        __syncthreads();
    }
}

// ---------------------------------------------------------------------------
// Merged Q/K/V projection: all three write fp16 hi only.
// ---------------------------------------------------------------------------
__global__ __launch_bounds__(256)
void proj_qkv(const float* __restrict__ bq, const float* __restrict__ bk,
              const float* __restrict__ bv)
{
    extern __shared__ __align__(16) char smem[];
    const int which = blockIdx.z;
    const int mBase = blockIdx.y * 128;
    const int nBase = blockIdx.x * 128;

    const __nv_bfloat16* wh = (which == 0) ? g_wqh : (which == 1) ? g_wkh : g_wvh;
    const __nv_bfloat16* wl = (which == 0) ? g_wql : (which == 1) ? g_wkl : g_wvl;
    const float* bias       = (which == 0) ? bq    : (which == 1) ? bk    : bv;
    __half* dh              = (which == 0) ? g_qh  : (which == 1) ? g_kh  : g_vh;

    float acc[4][4][4];
    #pragma unroll
    for (int i = 0; i < 4; i++)
        #pragma unroll
        for (int j = 0; j < 4; j++)
            #pragma unroll
            for (int e = 0; e < 4; e++) acc[i][j][e] = 0.0f;

    gemm_mainloop(acc,
                  g_xh + (size_t)mBase * Dc, g_xl + (size_t)mBase * Dc,
                  wh + (size_t)nBase * Dc, wl + (size_t)nBase * Dc,
                  Dc, Dc, Dc, smem);

    const int tid  = threadIdx.x;
    const int wid  = tid >> 5, lane = tid & 31;
    const int wm   = wid >> 2, wn = wid & 3;
    const int g    = lane >> 2, tg = lane & 3;

    #pragma unroll
    for (int mt = 0; mt < 4; mt++) {
        const int r0 = mBase + wm * 64 + mt * 16 + g;
        #pragma unroll
        for (int nt = 0; nt < 4; nt++) {
            const int c0 = nBase + wn * 32 + nt * 8 + tg * 2;
            const float b0 = bias[c0], b1 = bias[c0 + 1];
            #pragma unroll
            for (int half = 0; half < 2; half++) {
                const int r = r0 + half * 8;
                const float v0 = acc[mt][nt][half * 2 + 0] + b0;
                const float v1 = acc[mt][nt][half * 2 + 1] + b1;
                const int b  = r >> 11, s = r & (Sc - 1);
                const int h  = c0 >> 6, hd = c0 & (HDc - 1);
                const size_t idx = (((size_t)(b * Hc + h)) * Sc + s) * HDc + hd;
                *(uint32_t*)(dh + idx) = pack_h16(v0, v1);
            }
        }
    }
}

// ---------------------------------------------------------------------------
// Final O projection: out = AO * Wo^T + bo  (fp32 out; bf16 3-term)
// ---------------------------------------------------------------------------
__global__ __launch_bounds__(256)
void proj_o(const float* __restrict__ bias, float* __restrict__ outPlain)
{
    extern __shared__ __align__(16) char smem[];
    const int mBase = blockIdx.y * 128;
    const int nBase = blockIdx.x * 128;

    float acc[4][4][4];
    #pragma unroll
    for (int i = 0; i < 4; i++)
        #pragma unroll
        for (int j = 0; j < 4; j++)
            #pragma unroll
            for (int e = 0; e < 4; e++) acc[i][j][e] = 0.0f;

    gemm_mainloop(acc,
                  g_xh + (size_t)mBase * Dc, g_xl + (size_t)mBase * Dc,
                  g_woh + (size_t)nBase * Dc, g_wol + (size_t)nBase * Dc,
                  Dc, Dc, Dc, smem);

    const int tid  = threadIdx.x;
    const int wid  = tid >> 5, lane = tid & 31;
    const int wm   = wid >> 2, wn = wid & 3;
    const int g    = lane >> 2, tg = lane & 3;

    #pragma unroll
    for (int mt = 0; mt < 4; mt++) {
        const int r0 = mBase + wm * 64 + mt * 16 + g;
        #pragma unroll
        for (int nt = 0; nt < 4; nt++) {
            const int c0 = nBase + wn * 32 + nt * 8 + tg * 2;
            const float b0 = bias[c0], b1 = bias[c0 + 1];
            #pragma unroll
            for (int half = 0; half < 2; half++) {
                const int r = r0 + half * 8;
                const float v0 = acc[mt][nt][half * 2 + 0] + b0;
                const float v1 = acc[mt][nt][half * 2 + 1] + b1;
                *(float2*)(outPlain + (size_t)r * Dc + c0) = make_float2(v0, v1);
            }
        }
    }
}

// ---------------------------------------------------------------------------
// Fused flash attention, pure fp16:
//   S = Qh·Kh^T,  O = Ph·Vh   (all operands fp16, fp32 accumulate)
// 64 MMAs + 32 ldsm per warp-iter (was 128 + 64). smem 55296 B.
// ---------------------------------------------------------------------------
constexpr int TS        = 144;
constexpr int QTILE_B   = 128 * TS;                 // 18432
constexpr int KVTILE_B  = 64 * TS;                  // 9216
constexpr int KVSTAGE_B = 2 * KVTILE_B;             // 18432 (K + V)
constexpr int FLASH_SMEM = QTILE_B + 2 * KVSTAGE_B; // 55296

__global__ __launch_bounds__(256, 2)
void flash_kernel(const float* __restrict__ mask)
{
    extern __shared__ __align__(16) char smem[];
    const uint32_t sb = smem_to_u32(smem);
    const int tid = threadIdx.x, wid = tid >> 5, lane = tid & 31;
    const int g = lane >> 2, tg = lane & 3;
    const int qBase = blockIdx.x * 128;
    const int bh = blockIdx.y;
    const int b = bh >> 4, h = bh & (Hc - 1);

    const size_t bhOff = (size_t)bh * Sc * HDc;
    const __half* __restrict__ Qh = g_qh + bhOff + (size_t)qBase * HDc;
    const __half* __restrict__ Kh = g_kh + bhOff;
    const __half* __restrict__ Vh = g_vh + bhOff;

    const uint32_t sQH = sb;

    // ---- Q tile load (128 rows x 128B) ----
    #pragma unroll
    for (int i = 0; i < 4; i++) {
        const int c = tid + i * 256;
        const int r = c >> 3, cc = c & 7;
        const uint32_t so = (uint32_t)r * TS + cc * 16;
        cp_async16(sQH + so, Qh + (size_t)r * HDc + cc * 8);
    }
    cp_commit();

    // ---- K/V 64-key tile loader ----
    auto loadKV = [&](int kb, int st) {
        const uint32_t bufB = sb + QTILE_B + (uint32_t)st * KVSTAGE_B;
        const size_t base = (size_t)kb * 64 * HDc;
        {
            const int r = tid >> 2, cc = (tid & 3) * 2;   // 512 threads-worth in one pass
            const uint32_t so = (uint32_t)r * TS + cc * 16;
            const size_t go = base + (size_t)r * HDc + cc * 8;
            cp_async16(bufB            + so,      Kh + go);
            cp_async16(bufB            + so + 16, Kh + go + 8);
            cp_async16(bufB + KVTILE_B + so,      Vh + go);
            cp_async16(bufB + KVTILE_B + so + 16, Vh + go + 8);
        }
        cp_commit();
    };
    loadKV(0, 0);
    cp_wait0();
    __syncthreads();

    // ---- Q fragments, register-resident ----
    uint32_t qah[4][4];
    {
        const uint32_t arow = (uint32_t)(wid * 16 + (lane & 15));
        const uint32_t acolb = (uint32_t)((lane >> 4) * 16);
        #pragma unroll
        for (int kk = 0; kk < 4; kk++)
            ldsm_x4(qah[kk], sQH + arow * TS + kk * 32 + acolb);
    }

    float o[8][4];
    #pragma unroll
    for (int i = 0; i < 8; i++)
        #pragma unroll
        for (int e = 0; e < 4; e++) o[i][e] = 0.0f;
    float mrun0 = -3e38f, mrun1 = -3e38f, l0 = 0.0f, l1 = 0.0f;

    const float* __restrict__ M0 =
        mask + ((size_t)b * Sc + qBase + wid * 16 + g) * Sc;

    const uint32_t brow = (uint32_t)((lane & 7) + ((lane & 16) >> 1));
    const uint32_t bcolb = (uint32_t)((lane & 8) << 1);
    const uint32_t vrow = (uint32_t)((lane & 7) + (lane & 8));
    const uint32_t vcolb = (uint32_t)(lane & 16);

    for (int kb = 0; kb < 32; kb++) {
        if (kb + 1 < 32) { loadKV(kb + 1, (kb + 1) & 1); cp_wait1(); }
        else             { cp_wait0(); }
        __syncthreads();

        // prefetch this iteration's mask rows before the MMA phase
        const float* Mk0 = M0 + (size_t)kb * 64;
        if (tg == 0) {
            const float* pm8 = Mk0 + 8 * (size_t)Sc;
            asm volatile("prefetch.global.L1 [%0];" :: "l"(Mk0));
            asm volatile("prefetch.global.L1 [%0];" :: "l"(Mk0 + 32));
            asm volatile("prefetch.global.L1 [%0];" :: "l"(pm8));
            asm volatile("prefetch.global.L1 [%0];" :: "l"(pm8 + 32));
        }

        const uint32_t bufB = sb + QTILE_B + (uint32_t)(kb & 1) * KVSTAGE_B;
        const uint32_t sKH = bufB, sVH = bufB + KVTILE_B;

        // ---- S = Qh Kh^T ----
        float s[8][4];
        #pragma unroll
        for (int nt = 0; nt < 8; nt++)
            #pragma unroll
            for (int e = 0; e < 4; e++) s[nt][e] = 0.0f;

        #pragma unroll
        for (int p = 0; p < 4; p++) {
            #pragma unroll
            for (int kk = 0; kk < 4; kk++) {
                uint32_t tbh[4];
                const uint32_t off = (uint32_t)(16 * p + brow) * TS + kk * 32 + bcolb;
                ldsm_x4(tbh, sKH + off);
                mma_f16(s[2*p],   qah[kk], tbh[0], tbh[1]);
                mma_f16(s[2*p+1], qah[kk], tbh[2], tbh[3]);
            }
        }

        // ---- scale + mask + row max ----
        float mx0 = -3e38f, mx1 = -3e38f;
        #pragma unroll
        for (int nt = 0; nt < 8; nt++) {
            const int col = nt * 8 + tg * 2;
            const float2 a = *(const float2*)(Mk0 + col);
            const float2 c = *(const float2*)(Mk0 + 8 * (size_t)Sc + col);
            s[nt][0] = fmaf(s[nt][0], 0.125f, a.x);
            s[nt][1] = fmaf(s[nt][1], 0.125f, a.y);
            s[nt][2] = fmaf(s[nt][2], 0.125f, c.x);
            s[nt][3] = fmaf(s[nt][3], 0.125f, c.y);
            mx0 = fmaxf(mx0, fmaxf(s[nt][0], s[nt][1]));
            mx1 = fmaxf(mx1, fmaxf(s[nt][2], s[nt][3]));
        }
        #pragma unroll
        for (int d = 1; d < 4; d <<= 1) {
            mx0 = fmaxf(mx0, __shfl_xor_sync(0xffffffffu, mx0, d));
            mx1 = fmaxf(mx1, __shfl_xor_sync(0xffffffffu, mx1, d));
        }
        const float mn0 = fmaxf(mrun0, mx0), mn1 = fmaxf(mrun1, mx1);
        const float c0 = __expf(mrun0 - mn0), c1 = __expf(mrun1 - mn1);
        mrun0 = mn0; mrun1 = mn1;
        #pragma unroll
        for (int nt = 0; nt < 8; nt++) {
            o[nt][0] *= c0; o[nt][1] *= c0;
            o[nt][2] *= c1; o[nt][3] *= c1;
        }

        // ---- exp, pack P fp16, PV accumulate ----
        float rs0 = 0.0f, rs1 = 0.0f;
        #pragma unroll
        for (int j = 0; j < 4; j++) {
            const float p0 = __expf(s[2*j][0]   - mn0), p1 = __expf(s[2*j][1]   - mn0);
            const float p2 = __expf(s[2*j][2]   - mn1), p3 = __expf(s[2*j][3]   - mn1);
            const float p4 = __expf(s[2*j+1][0] - mn0), p5 = __expf(s[2*j+1][1] - mn0);
            const float p6 = __expf(s[2*j+1][2] - mn1), p7 = __expf(s[2*j+1][3] - mn1);
            rs0 += (p0 + p1) + (p4 + p5);
            rs1 += (p2 + p3) + (p6 + p7);

            uint32_t ah_[4];
            ah_[0] = pack_h16(p0, p1); ah_[1] = pack_h16(p2, p3);
            ah_[2] = pack_h16(p4, p5); ah_[3] = pack_h16(p6, p7);

            #pragma unroll
            for (int q = 0; q < 4; q++) {
                uint32_t tvh[4];
                const uint32_t off = (uint32_t)(16 * j + vrow) * TS + q * 32 + vcolb;
                ldsm_x4_trans(tvh, sVH + off);
                mma_f16(o[2*q],   ah_, tvh[0], tvh[1]);
                mma_f16(o[2*q+1], ah_, tvh[2], tvh[3]);
            }
        }
        #pragma unroll
        for (int d = 1; d < 4; d <<= 1) {
            rs0 += __shfl_xor_sync(0xffffffffu, rs0, d);
            rs1 += __shfl_xor_sync(0xffffffffu, rs1, d);
        }
        l0 = l0 * c0 + rs0;
        l1 = l1 * c1 + rs1;

        __syncthreads();
    }

    // ---- epilogue: O/l -> bf16 hi/lo into g_xh/g_xl [4096,1024] ----
    const float i0 = 1.0f / l0, i1 = 1.0f / l1;
    const int row0 = b * Sc + qBase + wid * 16 + g;
    #pragma unroll
    for (int nt = 0; nt < 8; nt++) {
        const int col = h * HDc + nt * 8 + tg * 2;
        const float v0 = o[nt][0] * i0, v1 = o[nt][1] * i0;
        const float v2 = o[nt][2] * i1, v3 = o[nt][3] * i1;
        const uint32_t h0 = pack_bf16(v0, v1), h1 = pack_bf16(v2, v3);
        *(uint32_t*)(g_xh + (size_t)row0 * Dc + col)       = h0;
        *(uint32_t*)(g_xl + (size_t)row0 * Dc + col)       = pack_lo(v0, v1, h0);
        *(uint32_t*)(g_xh + (size_t)(row0 + 8) * Dc + col) = h1;
        *(uint32_t*)(g_xl + (size_t)(row0 + 8) * Dc + col) = pack_lo(v2, v3, h1);
    }
}

// ---------------------------------------------------------------------------
// Launch: 5 kernels
// ---------------------------------------------------------------------------
extern "C" void kernel_launch(void* const* d_in, const int* in_sizes, int n_in,
                              void* d_out, int out_size)
{
    (void)in_sizes; (void)n_in; (void)out_size;

    const float* hs   = (const float*)d_in[0];
    const float* mask = (const float*)d_in[1];
    const float* Wq   = (const float*)d_in[2];
    const float* bq   = (const float*)d_in[3];
    const float* Wk   = (const float*)d_in[4];
    const float* bk   = (const float*)d_in[5];
    const float* Wv   = (const float*)d_in[6];
    const float* bv   = (const float*)d_in[7];
    const float* Wo   = (const float*)d_in[8];
    const float* bo   = (const float*)d_in[9];
    float* out = (float*)d_out;

    static bool attrDone = false;
    if (!attrDone) {
        cudaFuncSetAttribute(flash_kernel,
                             cudaFuncAttributeMaxDynamicSharedMemorySize, FLASH_SMEM);
        attrDone = true;
    }

    const int nX4 = Mc * Dc / 4;   // 1,048,576
    const int nW4 = Dc * Dc / 4;   // 262,144
    const dim3 gGemm(Dc / 128, Mc / 128);        // (8, 32)
    const dim3 gQKV(Dc / 128, Mc / 128, 3);      // (8, 32, 3)
    const dim3 gFlash(Sc / 128, Bc * Hc);        // (16, 32)
    const dim3 gW4((nW4 + 255) / 256, 4);

    split_x<<<(nX4 + 255) / 256, 256>>>(hs, nX4);
    split_w4<<<gW4, 256>>>(Wq, Wk, Wv, Wo, nW4);

    proj_qkv<<<gQKV, 256, SMEM_BYTES>>>(bq, bk, bv);

    flash_kernel<<<gFlash, 256, FLASH_SMEM>>>(mask);

    proj_o<<<gGemm, 256, SMEM_BYTES>>>(bo, out);
}

// round 17
// speedup vs baseline: 1.4448x; 1.0834x over previous
#include <cuda_runtime.h>
#include <cuda_bf16.h>
#include <cuda_fp16.h>
#include <cstdint>
#include <cstddef>

// Problem constants: B=2, S=2048, D=1024, H=16, HD=64
constexpr int Bc  = 2;
constexpr int Sc  = 2048;
constexpr int Dc  = 1024;
constexpr int Hc  = 16;
constexpr int HDc = 64;
constexpr int Mc  = Bc * Sc;   // 4096

// ---------------------------------------------------------------------------
// Static device scratch (fp16 everywhere; weights keep exact fp16 hi/lo pairs)
// ---------------------------------------------------------------------------
__device__ __half g_x  [(size_t)Mc * Dc];   // activations fp16 (reused for attn-out)

__device__ __half g_wqh[(size_t)Dc * Dc];
__device__ __half g_wql[(size_t)Dc * Dc];
__device__ __half g_wkh[(size_t)Dc * Dc];
__device__ __half g_wkl[(size_t)Dc * Dc];
__device__ __half g_wvh[(size_t)Dc * Dc];
__device__ __half g_wvl[(size_t)Dc * Dc];
__device__ __half g_woh[(size_t)Dc * Dc];
__device__ __half g_wol[(size_t)Dc * Dc];

__device__ __half g_qh[(size_t)Bc * Hc * Sc * HDc];   // Q (fp16)
__device__ __half g_kh[(size_t)Bc * Hc * Sc * HDc];   // K (fp16)
__device__ __half g_vh[(size_t)Bc * Hc * Sc * HDc];   // V (fp16)

// ---------------------------------------------------------------------------
// PTX helpers (baseline ISA only — compute_103 safe)
// ---------------------------------------------------------------------------
__device__ __forceinline__ uint32_t smem_to_u32(const void* p) {
    uint32_t a;
    asm("{ .reg .u64 t; cvta.to.shared.u64 t, %1; cvt.u32.u64 %0, t; }"
        : "=r"(a) : "l"(p));
    return a;
}
__device__ __forceinline__ void cp_async16(uint32_t dst, const void* src) {
    asm volatile("cp.async.cg.shared.global [%0], [%1], 16;"
                 :: "r"(dst), "l"(src) : "memory");
}
__device__ __forceinline__ void cp_commit() {
    asm volatile("cp.async.commit_group;" ::: "memory");
}
__device__ __forceinline__ void cp_wait0() {
    asm volatile("cp.async.wait_group 0;" ::: "memory");
}
__device__ __forceinline__ void cp_wait1() {
    asm volatile("cp.async.wait_group 1;" ::: "memory");
}
__device__ __forceinline__ void ldsm_x4(uint32_t (&r)[4], uint32_t addr) {
    asm volatile("ldmatrix.sync.aligned.m8n8.x4.shared.b16 {%0,%1,%2,%3}, [%4];"
                 : "=r"(r[0]), "=r"(r[1]), "=r"(r[2]), "=r"(r[3]) : "r"(addr));
}
__device__ __forceinline__ void ldsm_x4_trans(uint32_t (&r)[4], uint32_t addr) {
    asm volatile("ldmatrix.sync.aligned.m8n8.x4.trans.shared.b16 {%0,%1,%2,%3}, [%4];"
                 : "=r"(r[0]), "=r"(r[1]), "=r"(r[2]), "=r"(r[3]) : "r"(addr));
}
__device__ __forceinline__ void mma_f16(float (&d)[4], const uint32_t (&a)[4],
                                        const uint32_t b0, const uint32_t b1) {
    asm volatile(
        "mma.sync.aligned.m16n8k16.row.col.f32.f16.f16.f32 "
        "{%0,%1,%2,%3}, {%4,%5,%6,%7}, {%8,%9}, {%0,%1,%2,%3};"
        : "+f"(d[0]), "+f"(d[1]), "+f"(d[2]), "+f"(d[3])
        : "r"(a[0]), "r"(a[1]), "r"(a[2]), "r"(a[3]), "r"(b0), "r"(b1));
}
__device__ __forceinline__ uint32_t pack_h16(float x, float y) {
    __half2 t = __floats2half2_rn(x, y);
    return *reinterpret_cast<uint32_t*>(&t);
}
__device__ __forceinline__ uint32_t pack_h16lo(float x, float y, uint32_t hp) {
    __half2 hh = *reinterpret_cast<__half2*>(&hp);
    float2 hf = __half22float2(hh);
    __half2 t = __floats2half2_rn(x - hf.x, y - hf.y);
    return *reinterpret_cast<uint32_t*>(&t);
}

// ---------------------------------------------------------------------------
// Splits. split_x: fp32 -> fp16 (single buffer).
// split_w4: each weight -> fp16 hi + fp16 lo (exact 2-term representation).
// ---------------------------------------------------------------------------
__global__ void split_x(const float* __restrict__ src, int n4)
{
    const int i = blockIdx.x * blockDim.x + threadIdx.x;
    if (i >= n4) return;
    float4 v = ((const float4*)src)[i];
    uint2 H;
    H.x = pack_h16(v.x, v.y);
    H.y = pack_h16(v.z, v.w);
    ((uint2*)g_x)[i] = H;
}

__global__ void split_w4(const float* __restrict__ Wq, const float* __restrict__ Wk,
                         const float* __restrict__ Wv, const float* __restrict__ Wo,
                         int n4)
{
    const int i = blockIdx.x * blockDim.x + threadIdx.x;
    if (i >= n4) return;
    const int w = blockIdx.y;
    const float* src = (w == 0) ? Wq : (w == 1) ? Wk : (w == 2) ? Wv : Wo;
    __half* hi = (w == 0) ? g_wqh : (w == 1) ? g_wkh : (w == 2) ? g_wvh : g_woh;
    __half* lo = (w == 0) ? g_wql : (w == 1) ? g_wkl : (w == 2) ? g_wvl : g_wol;

    float4 v = ((const float4*)src)[i];
    uint2 H, L;
    H.x = pack_h16(v.x, v.y);
    H.y = pack_h16(v.z, v.w);
    L.x = pack_h16lo(v.x, v.y, H.x);
    L.y = pack_h16lo(v.z, v.w, H.y);
    ((uint2*)hi)[i] = H;
    ((uint2*)lo)[i] = L;
}

// ---------------------------------------------------------------------------
// fp16 2-term HMMA mainloop: acc += Xh * (Wh + Wl)^T  (== Xh * W exactly).
// 3 smem tiles of 128 rows x 80B (32 fp16 + 16B pad) = 30720 B.
// 8 warps (2m x 4n), 64x32 warp tile, BK=32. Single buffer, 2 CTAs/SM.
// 32 MMAs + 8 ldsm.x4 per ks (was 48 + 12 in bf16 3-term).
// ---------------------------------------------------------------------------
constexpr int SMEM_BYTES = 3 * 128 * 80;   // 30720

__device__ __forceinline__ void gemm_mainloop(
    float (&acc)[4][4][4],
    const __half* __restrict__ A,
    const __half* __restrict__ Bh, const __half* __restrict__ Bl,
    int ldA, int ldB, int K, char* smem)
{
    const int tid  = threadIdx.x;
    const int wid  = tid >> 5, lane = tid & 31;
    const int wm   = wid >> 2, wn = wid & 3;
    const uint32_t sb  = smem_to_u32(smem);
    const uint32_t sA = sb, sBh = sb + 10240, sBl = sb + 20480;

    const int lr = tid >> 2;
    const int lc = (tid & 3) * 8;

    const int arow = wm * 64 + (lane & 15);
    const int acol = (lane >> 4) << 3;
    const uint32_t aoff = (uint32_t)arow * 80 + acol * 2;
    const int brow = wn * 32 + (lane & 7) + ((lane & 16) >> 1);
    const int bcol = lane & 8;
    const uint32_t boff = (uint32_t)brow * 80 + bcol * 2;

    const int nchunks = K >> 5;
    for (int ch = 0; ch < nchunks; ch++) {
        const int k0 = ch * 32;
        #pragma unroll
        for (int it = 0; it < 2; it++) {
            const int r = lr + it * 64;
            const uint32_t so = (uint32_t)r * 80 + lc * 2;
            cp_async16(sA  + so, A  + (size_t)r * ldA + k0 + lc);
            cp_async16(sBh + so, Bh + (size_t)r * ldB + k0 + lc);
            cp_async16(sBl + so, Bl + (size_t)r * ldB + k0 + lc);
        }
        cp_commit();
        cp_wait0();
        __syncthreads();

        #pragma unroll
        for (int ks = 0; ks < 2; ks++) {
            uint32_t ah[4][4];
            uint32_t bh0[4], bh1[4], bl0[4], bl1[4];
            #pragma unroll
            for (int mt = 0; mt < 4; mt++) {
                const uint32_t off = aoff + (uint32_t)mt * 16 * 80 + ks * 32;
                ldsm_x4(ah[mt], sA + off);
            }
            #pragma unroll
            for (int p = 0; p < 2; p++) {
                const uint32_t off = boff + (uint32_t)p * 16 * 80 + ks * 32;
                uint32_t t[4];
                ldsm_x4(t, sBh + off);
                bh0[2*p] = t[0]; bh1[2*p] = t[1]; bh0[2*p+1] = t[2]; bh1[2*p+1] = t[3];
                ldsm_x4(t, sBl + off);
                bl0[2*p] = t[0]; bl1[2*p] = t[1]; bl0[2*p+1] = t[2]; bl1[2*p+1] = t[3];
            }
            // term-major: hi term across all 16 accs, then lo term
            #pragma unroll
            for (int mt = 0; mt < 4; mt++)
                #pragma unroll
                for (int nt = 0; nt < 4; nt++)
                    mma_f16(acc[mt][nt], ah[mt], bh0[nt], bh1[nt]);
            #pragma unroll
            for (int mt = 0; mt < 4; mt++)
                #pragma unroll
                for (int nt = 0; nt < 4; nt++)
                    mma_f16(acc[mt][nt], ah[mt], bl0[nt], bl1[nt]);
        }
        __syncthreads();
    }
}

// ---------------------------------------------------------------------------
// Merged Q/K/V projection: grid (8, 32, 3); writes fp16 Q/K/V [B,H,S,HD].
// ---------------------------------------------------------------------------
__global__ __launch_bounds__(256)
void proj_qkv(const float* __restrict__ bq, const float* __restrict__ bk,
              const float* __restrict__ bv)
{
    extern __shared__ __align__(16) char smem[];
    const int which = blockIdx.z;
    const int mBase = blockIdx.y * 128;
    const int nBase = blockIdx.x * 128;

    const __half* wh  = (which == 0) ? g_wqh : (which == 1) ? g_wkh : g_wvh;
    const __half* wl  = (which == 0) ? g_wql : (which == 1) ? g_wkl : g_wvl;
    const float* bias = (which == 0) ? bq    : (which == 1) ? bk    : bv;
    __half* dh        = (which == 0) ? g_qh  : (which == 1) ? g_kh  : g_vh;

    float acc[4][4][4];
    #pragma unroll
    for (int i = 0; i < 4; i++)
        #pragma unroll
        for (int j = 0; j < 4; j++)
            #pragma unroll
            for (int e = 0; e < 4; e++) acc[i][j][e] = 0.0f;

    gemm_mainloop(acc,
                  g_x + (size_t)mBase * Dc,
                  wh + (size_t)nBase * Dc, wl + (size_t)nBase * Dc,
                  Dc, Dc, Dc, smem);

    const int tid  = threadIdx.x;
    const int wid  = tid >> 5, lane = tid & 31;
    const int wm   = wid >> 2, wn = wid & 3;
    const int g    = lane >> 2, tg = lane & 3;

    #pragma unroll
    for (int mt = 0; mt < 4; mt++) {
        const int r0 = mBase + wm * 64 + mt * 16 + g;
        #pragma unroll
        for (int nt = 0; nt < 4; nt++) {
            const int c0 = nBase + wn * 32 + nt * 8 + tg * 2;
            const float b0 = bias[c0], b1 = bias[c0 + 1];
            #pragma unroll
            for (int half = 0; half < 2; half++) {
                const int r = r0 + half * 8;
                const float v0 = acc[mt][nt][half * 2 + 0] + b0;
                const float v1 = acc[mt][nt][half * 2 + 1] + b1;
                const int b  = r >> 11, s = r & (Sc - 1);
                const int h  = c0 >> 6, hd = c0 & (HDc - 1);
                const size_t idx = (((size_t)(b * Hc + h)) * Sc + s) * HDc + hd;
                *(uint32_t*)(dh + idx) = pack_h16(v0, v1);
            }
        }
    }
}

// ---------------------------------------------------------------------------
// Final O projection: out = AO * Wo^T + bo  (fp32 out)
// ---------------------------------------------------------------------------
__global__ __launch_bounds__(256)
void proj_o(const float* __restrict__ bias, float* __restrict__ outPlain)
{
    extern __shared__ __align__(16) char smem[];
    const int mBase = blockIdx.y * 128;
    const int nBase = blockIdx.x * 128;

    float acc[4][4][4];
    #pragma unroll
    for (int i = 0; i < 4; i++)
        #pragma unroll
        for (int j = 0; j < 4; j++)
            #pragma unroll
            for (int e = 0; e < 4; e++) acc[i][j][e] = 0.0f;

    gemm_mainloop(acc,
                  g_x + (size_t)mBase * Dc,
                  g_woh + (size_t)nBase * Dc, g_wol + (size_t)nBase * Dc,
                  Dc, Dc, Dc, smem);

    const int tid  = threadIdx.x;
    const int wid  = tid >> 5, lane = tid & 31;
    const int wm   = wid >> 2, wn = wid & 3;
    const int g    = lane >> 2, tg = lane & 3;

    #pragma unroll
    for (int mt = 0; mt < 4; mt++) {
        const int r0 = mBase + wm * 64 + mt * 16 + g;
        #pragma unroll
        for (int nt = 0; nt < 4; nt++) {
            const int c0 = nBase + wn * 32 + nt * 8 + tg * 2;
            const float b0 = bias[c0], b1 = bias[c0 + 1];
            #pragma unroll
            for (int half = 0; half < 2; half++) {
                const int r = r0 + half * 8;
                const float v0 = acc[mt][nt][half * 2 + 0] + b0;
                const float v1 = acc[mt][nt][half * 2 + 1] + b1;
                *(float2*)(outPlain + (size_t)r * Dc + c0) = make_float2(v0, v1);
            }
        }
    }
}

// ---------------------------------------------------------------------------
// Fused flash attention, pure fp16 (R16 proven): S = Q·K^T, O = P·V.
// Epilogue now writes AO as plain fp16 into g_x.
// ---------------------------------------------------------------------------
constexpr int TS        = 144;
constexpr int QTILE_B   = 128 * TS;                 // 18432
constexpr int KVTILE_B  = 64 * TS;                  // 9216
constexpr int KVSTAGE_B = 2 * KVTILE_B;             // 18432 (K + V)
constexpr int FLASH_SMEM = QTILE_B + 2 * KVSTAGE_B; // 55296

__global__ __launch_bounds__(256, 2)
void flash_kernel(const float* __restrict__ mask)
{
    extern __shared__ __align__(16) char smem[];
    const uint32_t sb = smem_to_u32(smem);
    const int tid = threadIdx.x, wid = tid >> 5, lane = tid & 31;
    const int g = lane >> 2, tg = lane & 3;
    const int qBase = blockIdx.x * 128;
    const int bh = blockIdx.y;
    const int b = bh >> 4, h = bh & (Hc - 1);

    const size_t bhOff = (size_t)bh * Sc * HDc;
    const __half* __restrict__ Qh = g_qh + bhOff + (size_t)qBase * HDc;
    const __half* __restrict__ Kh = g_kh + bhOff;
    const __half* __restrict__ Vh = g_vh + bhOff;

    const uint32_t sQH = sb;

    #pragma unroll
    for (int i = 0; i < 4; i++) {
        const int c = tid + i * 256;
        const int r = c >> 3, cc = c & 7;
        const uint32_t so = (uint32_t)r * TS + cc * 16;
        cp_async16(sQH + so, Qh + (size_t)r * HDc + cc * 8);
    }
    cp_commit();

    auto loadKV = [&](int kb, int st) {
        const uint32_t bufB = sb + QTILE_B + (uint32_t)st * KVSTAGE_B;
        const size_t base = (size_t)kb * 64 * HDc;
        {
            const int r = tid >> 2, cc = (tid & 3) * 2;
            const uint32_t so = (uint32_t)r * TS + cc * 16;
            const size_t go = base + (size_t)r * HDc + cc * 8;
            cp_async16(bufB            + so,      Kh + go);
            cp_async16(bufB            + so + 16, Kh + go + 8);
            cp_async16(bufB + KVTILE_B + so,      Vh + go);
            cp_async16(bufB + KVTILE_B + so + 16, Vh + go + 8);
        }
        cp_commit();
    };
    loadKV(0, 0);
    cp_wait0();
    __syncthreads();

    uint32_t qah[4][4];
    {
        const uint32_t arow = (uint32_t)(wid * 16 + (lane & 15));
        const uint32_t acolb = (uint32_t)((lane >> 4) * 16);
        #pragma unroll
        for (int kk = 0; kk < 4; kk++)
            ldsm_x4(qah[kk], sQH + arow * TS + kk * 32 + acolb);
    }

    float o[8][4];
    #pragma unroll
    for (int i = 0; i < 8; i++)
        #pragma unroll
        for (int e = 0; e < 4; e++) o[i][e] = 0.0f;
    float mrun0 = -3e38f, mrun1 = -3e38f, l0 = 0.0f, l1 = 0.0f;

    const float* __restrict__ M0 =
        mask + ((size_t)b * Sc + qBase + wid * 16 + g) * Sc;

    const uint32_t brow = (uint32_t)((lane & 7) + ((lane & 16) >> 1));
    const uint32_t bcolb = (uint32_t)((lane & 8) << 1);
    const uint32_t vrow = (uint32_t)((lane & 7) + (lane & 8));
    const uint32_t vcolb = (uint32_t)(lane & 16);

    for (int kb = 0; kb < 32; kb++) {
        if (kb + 1 < 32) { loadKV(kb + 1, (kb + 1) & 1); cp_wait1(); }
        else             { cp_wait0(); }
        __syncthreads();

        const float* Mk0 = M0 + (size_t)kb * 64;
        if (tg == 0) {
            const float* pm8 = Mk0 + 8 * (size_t)Sc;
            asm volatile("prefetch.global.L1 [%0];" :: "l"(Mk0));
            asm volatile("prefetch.global.L1 [%0];" :: "l"(Mk0 + 32));
            asm volatile("prefetch.global.L1 [%0];" :: "l"(pm8));
            asm volatile("prefetch.global.L1 [%0];" :: "l"(pm8 + 32));
        }

        const uint32_t bufB = sb + QTILE_B + (uint32_t)(kb & 1) * KVSTAGE_B;
        const uint32_t sKH = bufB, sVH = bufB + KVTILE_B;

        float s[8][4];
        #pragma unroll
        for (int nt = 0; nt < 8; nt++)
            #pragma unroll
            for (int e = 0; e < 4; e++) s[nt][e] = 0.0f;

        #pragma unroll
        for (int p = 0; p < 4; p++) {
            #pragma unroll
            for (int kk = 0; kk < 4; kk++) {
                uint32_t tbh[4];
                const uint32_t off = (uint32_t)(16 * p + brow) * TS + kk * 32 + bcolb;
                ldsm_x4(tbh, sKH + off);
                mma_f16(s[2*p],   qah[kk], tbh[0], tbh[1]);
                mma_f16(s[2*p+1], qah[kk], tbh[2], tbh[3]);
            }
        }

        float mx0 = -3e38f, mx1 = -3e38f;
        #pragma unroll
        for (int nt = 0; nt < 8; nt++) {
            const int col = nt * 8 + tg * 2;
            const float2 a = *(const float2*)(Mk0 + col);
            const float2 c = *(const float2*)(Mk0 + 8 * (size_t)Sc + col);
            s[nt][0] = fmaf(s[nt][0], 0.125f, a.x);
            s[nt][1] = fmaf(s[nt][1], 0.125f, a.y);
            s[nt][2] = fmaf(s[nt][2], 0.125f, c.x);
            s[nt][3] = fmaf(s[nt][3], 0.125f, c.y);
            mx0 = fmaxf(mx0, fmaxf(s[nt][0], s[nt][1]));
            mx1 = fmaxf(mx1, fmaxf(s[nt][2], s[nt][3]));
        }
        #pragma unroll
        for (int d = 1; d < 4; d <<= 1) {
            mx0 = fmaxf(mx0, __shfl_xor_sync(0xffffffffu, mx0, d));
            mx1 = fmaxf(mx1, __shfl_xor_sync(0xffffffffu, mx1, d));
        }
        const float mn0 = fmaxf(mrun0, mx0), mn1 = fmaxf(mrun1, mx1);
        const float c0 = __expf(mrun0 - mn0), c1 = __expf(mrun1 - mn1);
        mrun0 = mn0; mrun1 = mn1;
        #pragma unroll
        for (int nt = 0; nt < 8; nt++) {
            o[nt][0] *= c0; o[nt][1] *= c0;
            o[nt][2] *= c1; o[nt][3] *= c1;
        }

        float rs0 = 0.0f, rs1 = 0.0f;
        #pragma unroll
        for (int j = 0; j < 4; j++) {
            const float p0 = __expf(s[2*j][0]   - mn0), p1 = __expf(s[2*j][1]   - mn0);
            const float p2 = __expf(s[2*j][2]   - mn1), p3 = __expf(s[2*j][3]   - mn1);
            const float p4 = __expf(s[2*j+1][0] - mn0), p5 = __expf(s[2*j+1][1] - mn0);
            const float p6 = __expf(s[2*j+1][2] - mn1), p7 = __expf(s[2*j+1][3] - mn1);
            rs0 += (p0 + p1) + (p4 + p5);
            rs1 += (p2 + p3) + (p6 + p7);

            uint32_t ah_[4];
            ah_[0] = pack_h16(p0, p1); ah_[1] = pack_h16(p2, p3);
            ah_[2] = pack_h16(p4, p5); ah_[3] = pack_h16(p6, p7);

            #pragma unroll
            for (int q = 0; q < 4; q++) {
                uint32_t tvh[4];
                const uint32_t off = (uint32_t)(16 * j + vrow) * TS + q * 32 + vcolb;
                ldsm_x4_trans(tvh, sVH + off);
                mma_f16(o[2*q],   ah_, tvh[0], tvh[1]);
                mma_f16(o[2*q+1], ah_, tvh[2], tvh[3]);
            }
        }
        #pragma unroll
        for (int d = 1; d < 4; d <<= 1) {
            rs0 += __shfl_xor_sync(0xffffffffu, rs0, d);
            rs1 += __shfl_xor_sync(0xffffffffu, rs1, d);
        }
        l0 = l0 * c0 + rs0;
        l1 = l1 * c1 + rs1;

        __syncthreads();
    }

    // ---- epilogue: O/l -> fp16 into g_x [4096,1024] ----
    const float i0 = 1.0f / l0, i1 = 1.0f / l1;
    const int row0 = b * Sc + qBase + wid * 16 + g;
    #pragma unroll
    for (int nt = 0; nt < 8; nt++) {
        const int col = h * HDc + nt * 8 + tg * 2;
        *(uint32_t*)(g_x + (size_t)row0 * Dc + col) =
            pack_h16(o[nt][0] * i0, o[nt][1] * i0);
        *(uint32_t*)(g_x + (size_t)(row0 + 8) * Dc + col) =
            pack_h16(o[nt][2] * i1, o[nt][3] * i1);
    }
}

// ---------------------------------------------------------------------------
// Launch: 5 kernels
// ---------------------------------------------------------------------------
extern "C" void kernel_launch(void* const* d_in, const int* in_sizes, int n_in,
                              void* d_out, int out_size)
{
    (void)in_sizes; (void)n_in; (void)out_size;

    const float* hs   = (const float*)d_in[0];
    const float* mask = (const float*)d_in[1];
    const float* Wq   = (const float*)d_in[2];
    const float* bq   = (const float*)d_in[3];
    const float* Wk   = (const float*)d_in[4];
    const float* bk   = (const float*)d_in[5];
    const float* Wv   = (const float*)d_in[6];
    const float* bv   = (const float*)d_in[7];
    const float* Wo   = (const float*)d_in[8];
    const float* bo   = (const float*)d_in[9];
    float* out = (float*)d_out;

    static bool attrDone = false;
    if (!attrDone) {
        cudaFuncSetAttribute(flash_kernel,
                             cudaFuncAttributeMaxDynamicSharedMemorySize, FLASH_SMEM);
        attrDone = true;
    }

    const int nX4 = Mc * Dc / 4;   // 1,048,576
    const int nW4 = Dc * Dc / 4;   // 262,144
    const dim3 gGemm(Dc / 128, Mc / 128);        // (8, 32)
    const dim3 gQKV(Dc / 128, Mc / 128, 3);      // (8, 32, 3)
    const dim3 gFlash(Sc / 128, Bc * Hc);        // (16, 32)
    const dim3 gW4((nW4 + 255) / 256, 4);

    split_x<<<(nX4 + 255) / 256, 256>>>(hs, nX4);
    split_w4<<<gW4, 256>>>(Wq, Wk, Wv, Wo, nW4);

    proj_qkv<<<gQKV, 256, SMEM_BYTES>>>(bq, bk, bv);

    flash_kernel<<<gFlash, 256, FLASH_SMEM>>>(mask);

    proj_o<<<gGemm, 256, SMEM_BYTES>>>(bo, out);
}